// round 6
// baseline (speedup 1.0000x reference)
#include <cuda_runtime.h>
#include <cuda_fp16.h>
#include <cstdint>

// Problem constants
#define SB   1024
#define DD   64
#define BB   8
#define HH   8
#define CC   21
#define OUT_ELEMS (BB*HH*SB*DD)
#define KPU  36      // K/Vt smem pitch in uints (72 halves) -> conflict-free
#define VPH  72      // Vt pitch in halves

// ---------------------------------------------------------------------------
// Fragment-tiled scratch: [bh(64)][qg(64)][kgrp(128)][lane(32)] x uint2 (8B)
//   lane (g,tg):  .x = half2 bias/e for (row qg*16+g,   keys kgrp*8+2tg..+1)
//                 .y = half2 bias/e for (row qg*16+g+8, same keys)
// Holds fp16 bias (written by k_bias), overwritten in-place with fp16 e by
// k_flash pass 1, consumed by pass 2. 128 MiB.
// ---------------------------------------------------------------------------
__device__ uint2 g_scr[64ull * 64 * 128 * 32];

__device__ __forceinline__ unsigned packh2(float x, float y) {
    __half2 h = __float22half2_rn(make_float2(x, y));
    return *reinterpret_cast<unsigned*>(&h);
}

__device__ __forceinline__ void mma_f16(float c[4], const unsigned a[4],
                                        unsigned b0, unsigned b1) {
    asm volatile(
        "mma.sync.aligned.m16n8k16.row.col.f32.f16.f16.f32 "
        "{%0,%1,%2,%3}, {%4,%5,%6,%7}, {%8,%9}, {%0,%1,%2,%3};\n"
        : "+f"(c[0]), "+f"(c[1]), "+f"(c[2]), "+f"(c[3])
        : "r"(a[0]), "r"(a[1]), "r"(a[2]), "r"(a[3]), "r"(b0), "r"(b1));
}

// ---------------------------------------------------------------------------
// Kernel 1: bias = sum_c dtw*W + b - 4 (exp offset folded); masked -> -60000.
// Each thread handles rows (q, q+8) and one key pair -> writes complete
// fragment-lane uint2 per head. Warp stores are sector-complete.
// ---------------------------------------------------------------------------
__global__ __launch_bounds__(256) void k_bias(
    const float* __restrict__ dtw, const int* __restrict__ mask,
    const float* __restrict__ W, const float* __restrict__ bvec)
{
    __shared__ float Ws[HH * CC];
    __shared__ float bs[HH];
    int t = threadIdx.x;
    if (t < HH * CC) Ws[t] = W[t];
    if (t < HH)      bs[t] = bvec[t] - 4.0f;   // exp offset folded
    __syncthreads();

    unsigned idx = blockIdx.x * 256u + (unsigned)t;  // [bb:3][qg:6][r:3][k2:9]
    int k2 = idx & 511;
    int r  = (idx >> 9) & 7;
    int qg = (idx >> 12) & 63;
    int bb = idx >> 18;
    int qlo = qg * 16 + r;

    const float2* dlo = reinterpret_cast<const float2*>(dtw)
                        + ((size_t)(bb * CC) * SB + qlo) * 512 + k2;
    const int2* mp = reinterpret_cast<const int2*>(mask)
                     + ((size_t)bb * SB + qlo) * 512 + k2;
    int2 mlo = mp[0];
    int2 mhi = mp[8 * 512];

    float2 alo[HH], ahi[HH];
#pragma unroll
    for (int h = 0; h < HH; h++) {
        alo[h] = make_float2(bs[h], bs[h]);
        ahi[h] = make_float2(bs[h], bs[h]);
    }

#pragma unroll
    for (int c = 0; c < CC; c++) {
        float2 dl = __ldcs(dlo + (size_t)c * (SB * 512));
        float2 dh = __ldcs(dlo + (size_t)c * (SB * 512) + 8 * 512);
#pragma unroll
        for (int h = 0; h < HH; h++) {
            float w = Ws[h * CC + c];
            alo[h].x += w * dl.x; alo[h].y += w * dl.y;
            ahi[h].x += w * dh.x; ahi[h].y += w * dh.y;
        }
    }

    size_t slot = ((size_t)(bb * HH) * 64 + qg) * 128 * 32
                + (size_t)(k2 >> 2) * 32 + r * 4 + (k2 & 3);
#pragma unroll
    for (int h = 0; h < HH; h++) {
        uint2 v;
        v.x = packh2(mlo.x ? alo[h].x : -60000.f, mlo.y ? alo[h].y : -60000.f);
        v.y = packh2(mhi.x ? ahi[h].x : -60000.f, mhi.y ? ahi[h].y : -60000.f);
        g_scr[slot + (size_t)h * (64 * 128 * 32)] = v;
    }
}

// ---------------------------------------------------------------------------
// Kernel 2: single-QK-pass attention.
// Pass 1: s = QK/8 + bias; e = exp(s) (offset pre-folded); l += e;
//         e (fp16) overwrites bias in scratch.
// Pass 2: attention = e/l (fp32, gmem); O += e*V via mma (raw fp16 e as
//         A-frag); O scaled by 1/l at the end.  smem = 9.2 KB.
// ---------------------------------------------------------------------------
__global__ __launch_bounds__(256, 3) void k_flash(
    const float* __restrict__ Q, const float* __restrict__ K,
    const float* __restrict__ V, float* __restrict__ out)
{
    __shared__ unsigned Bu[64 * KPU];   // K chunk (pass 1) / Vt chunk (pass 2)

    const int tid  = threadIdx.x;
    const int warp = tid >> 5;
    const int lane = tid & 31;
    const int g    = lane >> 2;
    const int tg   = lane & 3;

    const int bh = blockIdx.x >> 3;
    const int q8 = blockIdx.x & 7;
    const int qg = q8 * 8 + warp;
    const int wb = warp * 16;

    const float* Qg  = Q + ((size_t)bh * SB + q8 * 128 + wb) * DD;
    const float4* Kg4 = reinterpret_cast<const float4*>(K + (size_t)bh * SB * DD);
    const float4* Vg4 = reinterpret_cast<const float4*>(V + (size_t)bh * SB * DD);
    float* attnW = out + OUT_ELEMS + ((size_t)bh * SB + q8 * 128 + wb) * SB;
    float* outW  = out + ((size_t)bh * SB + q8 * 128 + wb) * DD;
    uint2* scrW  = g_scr + ((size_t)bh * 64 + qg) * 128 * 32 + lane;

    // ---- Q fragments (rows wb+g, wb+g+8), 1/8 folded ----
    unsigned aq[4][4];
#pragma unroll
    for (int ks = 0; ks < 4; ks++) {
        float2 v0 = *reinterpret_cast<const float2*>(Qg + g * DD + ks * 16 + tg * 2);
        float2 v1 = *reinterpret_cast<const float2*>(Qg + (g + 8) * DD + ks * 16 + tg * 2);
        float2 v2 = *reinterpret_cast<const float2*>(Qg + g * DD + ks * 16 + 8 + tg * 2);
        float2 v3 = *reinterpret_cast<const float2*>(Qg + (g + 8) * DD + ks * 16 + 8 + tg * 2);
        aq[ks][0] = packh2(v0.x * 0.125f, v0.y * 0.125f);
        aq[ks][1] = packh2(v1.x * 0.125f, v1.y * 0.125f);
        aq[ks][2] = packh2(v2.x * 0.125f, v2.y * 0.125f);
        aq[ks][3] = packh2(v3.x * 0.125f, v3.y * 0.125f);
    }

    // ---- Pass 1: e = exp(QK/8 + bias'); l accumulation; e -> scratch ----
    float l0 = 0.f, l1 = 0.f;
    for (int ch = 0; ch < 16; ++ch) {
        __syncthreads();
#pragma unroll
        for (int j = 0; j < 4; j++) {
            int i = tid + j * 256;
            int r = i >> 4, c = i & 15;
            float4 v = Kg4[(size_t)(ch * 64 + r) * 16 + c];
            Bu[r * KPU + c * 2]     = packh2(v.x, v.y);
            Bu[r * KPU + c * 2 + 1] = packh2(v.z, v.w);
        }
        __syncthreads();

#pragma unroll
        for (int t8 = 0; t8 < 8; t8++) {
            float c4[4] = {0.f, 0.f, 0.f, 0.f};
#pragma unroll
            for (int ks = 0; ks < 4; ks++) {
                unsigned b0 = Bu[(t8 * 8 + g) * KPU + ks * 8 + tg];
                unsigned b1 = Bu[(t8 * 8 + g) * KPU + ks * 8 + tg + 4];
                mma_f16(c4, aq[ks], b0, b1);
            }
            uint2 bf = scrW[(ch * 8 + t8) * 32];
            float2 f0 = __half22float2(*reinterpret_cast<__half2*>(&bf.x));
            float2 f1 = __half22float2(*reinterpret_cast<__half2*>(&bf.y));
            float e0 = __expf(c4[0] + f0.x);
            float e1 = __expf(c4[1] + f0.y);
            float e2 = __expf(c4[2] + f1.x);
            float e3 = __expf(c4[3] + f1.y);
            l0 += e0 + e1;
            l1 += e2 + e3;
            uint2 st;
            st.x = packh2(e0, e1);
            st.y = packh2(e2, e3);
            scrW[(ch * 8 + t8) * 32] = st;
        }
    }

    l0 += __shfl_xor_sync(0xffffffffu, l0, 1);
    l0 += __shfl_xor_sync(0xffffffffu, l0, 2);
    l1 += __shfl_xor_sync(0xffffffffu, l1, 1);
    l1 += __shfl_xor_sync(0xffffffffu, l1, 2);
    const float r0 = 1.f / l0, r1 = 1.f / l1;

    // ---- Pass 2: attention = e/l; O = (sum e*V) / l ----
    float oc[8][4];
#pragma unroll
    for (int dt = 0; dt < 8; dt++)
#pragma unroll
        for (int j = 0; j < 4; j++) oc[dt][j] = 0.f;

    __half* vh = reinterpret_cast<__half*>(Bu);

    for (int ch = 0; ch < 16; ++ch) {
        __syncthreads();
#pragma unroll
        for (int j = 0; j < 4; j++) {
            int i = tid + j * 256;
            int r = i & 63, c = i >> 6;
            float4 v = Vg4[(size_t)(ch * 64 + r) * 16 + c];
            vh[(c * 4 + 0) * VPH + r] = __float2half_rn(v.x);
            vh[(c * 4 + 1) * VPH + r] = __float2half_rn(v.y);
            vh[(c * 4 + 2) * VPH + r] = __float2half_rn(v.z);
            vh[(c * 4 + 3) * VPH + r] = __float2half_rn(v.w);
        }
        __syncthreads();

#pragma unroll
        for (int kg = 0; kg < 4; kg++) {
            unsigned ap[4];
#pragma unroll
            for (int hf = 0; hf < 2; hf++) {
                int t8 = kg * 2 + hf;
                int n0 = ch * 64 + t8 * 8;
                uint2 ef = scrW[(ch * 8 + t8) * 32];
                ap[hf * 2]     = ef.x;
                ap[hf * 2 + 1] = ef.y;
                float2 f0 = __half22float2(*reinterpret_cast<__half2*>(&ef.x));
                float2 f1 = __half22float2(*reinterpret_cast<__half2*>(&ef.y));
                __stcs(reinterpret_cast<float2*>(attnW + (size_t)g * SB + n0 + tg * 2),
                       make_float2(f0.x * r0, f0.y * r0));
                __stcs(reinterpret_cast<float2*>(attnW + (size_t)(g + 8) * SB + n0 + tg * 2),
                       make_float2(f1.x * r1, f1.y * r1));
            }
#pragma unroll
            for (int dt = 0; dt < 8; dt++) {
                unsigned b0 = Bu[(dt * 8 + g) * KPU + kg * 8 + tg];
                unsigned b1 = Bu[(dt * 8 + g) * KPU + kg * 8 + tg + 4];
                mma_f16(oc[dt], ap, b0, b1);
            }
        }
    }

    // ---- write O (scaled by 1/l) ----
#pragma unroll
    for (int dt = 0; dt < 8; dt++) {
        int col = dt * 8 + tg * 2;
        *reinterpret_cast<float2*>(outW + (size_t)g * DD + col) =
            make_float2(oc[dt][0] * r0, oc[dt][1] * r0);
        *reinterpret_cast<float2*>(outW + (size_t)(g + 8) * DD + col) =
            make_float2(oc[dt][2] * r1, oc[dt][3] * r1);
    }
}

// ---------------------------------------------------------------------------
extern "C" void kernel_launch(void* const* d_in, const int* in_sizes, int n_in,
                              void* d_out, int out_size)
{
    const float* Q    = (const float*)d_in[0];
    const float* K    = (const float*)d_in[1];
    const float* V    = (const float*)d_in[2];
    const float* dtw  = (const float*)d_in[3];
    const int*   mask = (const int*)d_in[4];
    const float* W    = (const float*)d_in[5];
    const float* bvec = (const float*)d_in[6];
    float*       out  = (float*)d_out;

    k_bias<<<8192, 256>>>(dtw, mask, W, bvec);
    k_flash<<<BB * HH * (SB / 128), 256>>>(Q, K, V, out);
}

// round 7
// speedup vs baseline: 1.2408x; 1.2408x over previous
#include <cuda_runtime.h>
#include <cuda_fp16.h>
#include <cstdint>

// Problem constants
#define SB   1024
#define DD   64
#define BB   8
#define HH   8
#define CC   21
#define OUT_ELEMS (BB*HH*SB*DD)
#define KPU  36      // K smem pitch in uints (72 halves); 144B rows -> LDSM conflict-free
#define VPU  68      // Vt smem pitch in uints (136 halves); 272B rows -> conflict-free
#define VPH  136

// ---------------------------------------------------------------------------
// Fragment-tiled scratch: [bh(64)][qg(64)][kgrp(128)][lane(32)] x uint2 (8B)
//   lane (g,tg):  .x = half2 bias/e for (row qg*16+g,   keys kgrp*8+2tg..+1)
//                 .y = half2 bias/e for (row qg*16+g+8, same keys)
// fp16 bias written by k_bias, overwritten in place with fp16 e by k_flash
// pass 1, consumed by pass 2. 128 MiB. Declared uint4 for 16B-aligned stores.
// ---------------------------------------------------------------------------
__device__ uint4 g_scr[64ull * 64 * 2048];

__device__ __forceinline__ unsigned packh2(float x, float y) {
    __half2 h = __float22half2_rn(make_float2(x, y));
    return *reinterpret_cast<unsigned*>(&h);
}

__device__ __forceinline__ void mma_f16(float c[4], const unsigned a[4],
                                        unsigned b0, unsigned b1) {
    asm volatile(
        "mma.sync.aligned.m16n8k16.row.col.f32.f16.f16.f32 "
        "{%0,%1,%2,%3}, {%4,%5,%6,%7}, {%8,%9}, {%0,%1,%2,%3};\n"
        : "+f"(c[0]), "+f"(c[1]), "+f"(c[2]), "+f"(c[3])
        : "r"(a[0]), "r"(a[1]), "r"(a[2]), "r"(a[3]), "r"(b0), "r"(b1));
}

__device__ __forceinline__ void ldsm4(unsigned r[4], unsigned saddr) {
    asm volatile(
        "ldmatrix.sync.aligned.m8n8.x4.shared.b16 {%0,%1,%2,%3}, [%4];\n"
        : "=r"(r[0]), "=r"(r[1]), "=r"(r[2]), "=r"(r[3]) : "r"(saddr));
}

// ---------------------------------------------------------------------------
// Kernel 1: bias = sum_c dtw*W + b - 4 (exp offset folded); masked -> -60000.
// Thread covers rows (q, q+8) x 4 keys -> one uint4 scratch store per head.
// ---------------------------------------------------------------------------
__global__ __launch_bounds__(256) void k_bias(
    const float* __restrict__ dtw, const int* __restrict__ mask,
    const float* __restrict__ W, const float* __restrict__ bvec)
{
    __shared__ float Ws[HH * CC];
    __shared__ float bs[HH];
    int t = threadIdx.x;
    if (t < HH * CC) Ws[t] = W[t];
    if (t < HH)      bs[t] = bvec[t] - 4.0f;   // exp offset folded
    __syncthreads();

    unsigned idx = blockIdx.x * 256u + (unsigned)t;  // [bb:3][qg:6][r:3][k4:8]
    int k4 = idx & 255;            // key quad (4 keys)
    int r  = (idx >> 8) & 7;
    int qg = (idx >> 11) & 63;
    int bb = idx >> 17;
    int qlo = qg * 16 + r;

    const float4* dp = reinterpret_cast<const float4*>(dtw)
                       + ((size_t)(bb * CC) * SB + qlo) * 256 + k4;
    const int4* mp = reinterpret_cast<const int4*>(mask)
                     + ((size_t)bb * SB + qlo) * 256 + k4;
    int4 mlo = mp[0];
    int4 mhi = mp[8 * 256];

    float4 a[HH];
    uint2  lo[HH];

    // row qlo
#pragma unroll
    for (int h = 0; h < HH; h++) a[h] = make_float4(bs[h], bs[h], bs[h], bs[h]);
#pragma unroll
    for (int c = 0; c < CC; c++) {
        float4 d = __ldcs(dp + (size_t)c * (SB * 256));
#pragma unroll
        for (int h = 0; h < HH; h++) {
            float w = Ws[h * CC + c];
            a[h].x += w * d.x; a[h].y += w * d.y;
            a[h].z += w * d.z; a[h].w += w * d.w;
        }
    }
#pragma unroll
    for (int h = 0; h < HH; h++) {
        lo[h].x = packh2(mlo.x ? a[h].x : -60000.f, mlo.y ? a[h].y : -60000.f);
        lo[h].y = packh2(mlo.z ? a[h].z : -60000.f, mlo.w ? a[h].w : -60000.f);
    }

    // row qlo+8
#pragma unroll
    for (int h = 0; h < HH; h++) a[h] = make_float4(bs[h], bs[h], bs[h], bs[h]);
#pragma unroll
    for (int c = 0; c < CC; c++) {
        float4 d = __ldcs(dp + (size_t)c * (SB * 256) + 8 * 256);
#pragma unroll
        for (int h = 0; h < HH; h++) {
            float w = Ws[h * CC + c];
            a[h].x += w * d.x; a[h].y += w * d.y;
            a[h].z += w * d.z; a[h].w += w * d.w;
        }
    }

    // uint4 slot: [(bh,qg)]*2048 + kgrp*16 + r*2 + (k4&1)
    size_t base4 = ((size_t)(bb * HH) * 64 + qg) * 2048
                 + (size_t)(k4 >> 1) * 16 + r * 2 + (k4 & 1);
#pragma unroll
    for (int h = 0; h < HH; h++) {
        uint4 v;
        v.x = lo[h].x;
        v.y = packh2(mhi.x ? a[h].x : -60000.f, mhi.y ? a[h].y : -60000.f);
        v.z = lo[h].y;
        v.w = packh2(mhi.z ? a[h].z : -60000.f, mhi.w ? a[h].w : -60000.f);
        g_scr[base4 + (size_t)h * (64 * 2048)] = v;
    }
}

// ---------------------------------------------------------------------------
// Kernel 2: single-QK-pass attention, ldmatrix fragment loads, 128-key chunks.
// Pass 1: e = exp(QK/8 + bias') -> scratch (fp16), l accumulated.
// Pass 2: attention = e/l (fp32); O = (sum e*V)/l via mma.
// ---------------------------------------------------------------------------
__global__ __launch_bounds__(256, 3) void k_flash(
    const float* __restrict__ Q, const float* __restrict__ K,
    const float* __restrict__ V, float* __restrict__ out)
{
    __shared__ unsigned Bu[128 * KPU];   // K chunk (pass1) / Vt chunk (pass2)

    const int tid  = threadIdx.x;
    const int warp = tid >> 5;
    const int lane = tid & 31;
    const int g    = lane >> 2;
    const int tg   = lane & 3;

    const int bh = blockIdx.x >> 3;
    const int q8 = blockIdx.x & 7;
    const int qg = q8 * 8 + warp;
    const int wb = warp * 16;

    const float* Qg   = Q + ((size_t)bh * SB + q8 * 128 + wb) * DD;
    const float4* Kg4 = reinterpret_cast<const float4*>(K + (size_t)bh * SB * DD);
    const float4* Vg4 = reinterpret_cast<const float4*>(V + (size_t)bh * SB * DD);
    float* attnW = out + OUT_ELEMS + ((size_t)bh * SB + q8 * 128 + wb) * SB;
    float* outW  = out + ((size_t)bh * SB + q8 * 128 + wb) * DD;
    uint2* scrW  = reinterpret_cast<uint2*>(g_scr)
                 + ((size_t)bh * 64 + qg) * 4096 + lane;

    const unsigned sB = (unsigned)__cvta_generic_to_shared(Bu);

    // ---- Q fragments (rows wb+g, wb+g+8), 1/8 folded ----
    unsigned aq[4][4];
#pragma unroll
    for (int ks = 0; ks < 4; ks++) {
        float2 v0 = *reinterpret_cast<const float2*>(Qg + g * DD + ks * 16 + tg * 2);
        float2 v1 = *reinterpret_cast<const float2*>(Qg + (g + 8) * DD + ks * 16 + tg * 2);
        float2 v2 = *reinterpret_cast<const float2*>(Qg + g * DD + ks * 16 + 8 + tg * 2);
        float2 v3 = *reinterpret_cast<const float2*>(Qg + (g + 8) * DD + ks * 16 + 8 + tg * 2);
        aq[ks][0] = packh2(v0.x * 0.125f, v0.y * 0.125f);
        aq[ks][1] = packh2(v1.x * 0.125f, v1.y * 0.125f);
        aq[ks][2] = packh2(v2.x * 0.125f, v2.y * 0.125f);
        aq[ks][3] = packh2(v3.x * 0.125f, v3.y * 0.125f);
    }

    // ---- Pass 1 ----
    const unsigned laneK = (lane & 7) * (KPU * 4) + (lane >> 3) * 16;
    float l0 = 0.f, l1 = 0.f;
    for (int ch = 0; ch < 8; ++ch) {
        __syncthreads();
#pragma unroll
        for (int j = 0; j < 8; j++) {          // 2048 float4 per 128-key chunk
            int i = tid + j * 256;
            int r = i >> 4, c = i & 15;
            float4 v = Kg4[(size_t)(ch * 128 + r) * 16 + c];
            Bu[r * KPU + c * 2]     = packh2(v.x, v.y);
            Bu[r * KPU + c * 2 + 1] = packh2(v.z, v.w);
        }
        __syncthreads();

#pragma unroll
        for (int t8 = 0; t8 < 16; t8++) {
            unsigned qv[4], qw[4];
            ldsm4(qv, sB + t8 * (8 * KPU * 4) + laneK);
            ldsm4(qw, sB + t8 * (8 * KPU * 4) + laneK + 64);
            float c4[4] = {0.f, 0.f, 0.f, 0.f};
            mma_f16(c4, aq[0], qv[0], qv[1]);
            mma_f16(c4, aq[1], qv[2], qv[3]);
            mma_f16(c4, aq[2], qw[0], qw[1]);
            mma_f16(c4, aq[3], qw[2], qw[3]);

            uint2 bf = scrW[(ch * 16 + t8) * 32];
            float2 f0 = __half22float2(*reinterpret_cast<__half2*>(&bf.x));
            float2 f1 = __half22float2(*reinterpret_cast<__half2*>(&bf.y));
            float e0 = __expf(c4[0] + f0.x);
            float e1 = __expf(c4[1] + f0.y);
            float e2 = __expf(c4[2] + f1.x);
            float e3 = __expf(c4[3] + f1.y);
            l0 += e0 + e1;
            l1 += e2 + e3;
            uint2 st;
            st.x = packh2(e0, e1);
            st.y = packh2(e2, e3);
            scrW[(ch * 16 + t8) * 32] = st;
        }
    }

    l0 += __shfl_xor_sync(0xffffffffu, l0, 1);
    l0 += __shfl_xor_sync(0xffffffffu, l0, 2);
    l1 += __shfl_xor_sync(0xffffffffu, l1, 1);
    l1 += __shfl_xor_sync(0xffffffffu, l1, 2);
    const float r0 = 1.f / l0, r1 = 1.f / l1;

    // ---- Pass 2 ----
    float oc[8][4];
#pragma unroll
    for (int dt = 0; dt < 8; dt++)
#pragma unroll
        for (int j = 0; j < 4; j++) oc[dt][j] = 0.f;

    __half* vh = reinterpret_cast<__half*>(Bu);
    const unsigned laneV = (((lane >> 4) & 1) * 8 + (lane & 7)) * (VPU * 4)
                         + ((lane >> 3) & 1) * 16;

    for (int ch = 0; ch < 8; ++ch) {
        __syncthreads();
#pragma unroll
        for (int j = 0; j < 8; j++) {          // Vt: [dim][key], 128 keys
            int i = tid + j * 256;
            int r = i & 127, c = i >> 7;
            float4 v = Vg4[(size_t)(ch * 128 + r) * 16 + c];
            vh[(c * 4 + 0) * VPH + r] = __float2half_rn(v.x);
            vh[(c * 4 + 1) * VPH + r] = __float2half_rn(v.y);
            vh[(c * 4 + 2) * VPH + r] = __float2half_rn(v.z);
            vh[(c * 4 + 3) * VPH + r] = __float2half_rn(v.w);
        }
        __syncthreads();

#pragma unroll
        for (int kg = 0; kg < 8; kg++) {       // 16-key groups
            uint2 ef0 = scrW[(ch * 16 + 2 * kg) * 32];
            uint2 ef1 = scrW[(ch * 16 + 2 * kg + 1) * 32];
            unsigned ap[4] = {ef0.x, ef0.y, ef1.x, ef1.y};

            {   // attention stores (fp32 = e/l)
                int n0 = ch * 128 + kg * 16;
                float2 f0 = __half22float2(*reinterpret_cast<__half2*>(&ef0.x));
                float2 f1 = __half22float2(*reinterpret_cast<__half2*>(&ef0.y));
                float2 f2 = __half22float2(*reinterpret_cast<__half2*>(&ef1.x));
                float2 f3 = __half22float2(*reinterpret_cast<__half2*>(&ef1.y));
                __stcs(reinterpret_cast<float2*>(attnW + (size_t)g * SB + n0 + tg * 2),
                       make_float2(f0.x * r0, f0.y * r0));
                __stcs(reinterpret_cast<float2*>(attnW + (size_t)(g + 8) * SB + n0 + tg * 2),
                       make_float2(f1.x * r1, f1.y * r1));
                __stcs(reinterpret_cast<float2*>(attnW + (size_t)g * SB + n0 + 8 + tg * 2),
                       make_float2(f2.x * r0, f2.y * r0));
                __stcs(reinterpret_cast<float2*>(attnW + (size_t)(g + 8) * SB + n0 + 8 + tg * 2),
                       make_float2(f3.x * r1, f3.y * r1));
            }

#pragma unroll
            for (int dp2 = 0; dp2 < 4; dp2++) {
                unsigned v[4];
                ldsm4(v, sB + dp2 * (16 * VPU * 4) + kg * 32 + laneV);
                mma_f16(oc[dp2 * 2],     ap, v[0], v[1]);
                mma_f16(oc[dp2 * 2 + 1], ap, v[2], v[3]);
            }
        }
    }

    // ---- write O (scaled by 1/l) ----
#pragma unroll
    for (int dt = 0; dt < 8; dt++) {
        int col = dt * 8 + tg * 2;
        *reinterpret_cast<float2*>(outW + (size_t)g * DD + col) =
            make_float2(oc[dt][0] * r0, oc[dt][1] * r0);
        *reinterpret_cast<float2*>(outW + (size_t)(g + 8) * DD + col) =
            make_float2(oc[dt][2] * r1, oc[dt][3] * r1);
    }
}

// ---------------------------------------------------------------------------
extern "C" void kernel_launch(void* const* d_in, const int* in_sizes, int n_in,
                              void* d_out, int out_size)
{
    const float* Q    = (const float*)d_in[0];
    const float* K    = (const float*)d_in[1];
    const float* V    = (const float*)d_in[2];
    const float* dtw  = (const float*)d_in[3];
    const int*   mask = (const int*)d_in[4];
    const float* W    = (const float*)d_in[5];
    const float* bvec = (const float*)d_in[6];
    float*       out  = (float*)d_out;

    k_bias<<<4096, 256>>>(dtw, mask, W, bvec);
    k_flash<<<BB * HH * (SB / 128), 256>>>(Q, K, V, out);
}

// round 8
// speedup vs baseline: 1.4235x; 1.1473x over previous
#include <cuda_runtime.h>
#include <cuda_fp16.h>
#include <cstdint>

// Problem constants
#define SB   1024
#define DD   64
#define BB   8
#define HH   8
#define CC   21
#define OUT_ELEMS (BB*HH*SB*DD)
#define KPU  36      // smem chunk pitch in uints (72 halves = 144B) -> LDSM conflict-free

// ---------------------------------------------------------------------------
// Scratch 1: fragment-tiled bias/e, [bh(64)][qg(64)][kgrp(128)][lane(32)] uint2.
// Scratch 2: fp16 K and V, [2][bh(64)][s(1024)][d(64)].
// ---------------------------------------------------------------------------
__device__ uint4  g_scr[64ull * 64 * 2048];          // 128 MiB
__device__ __half g_kv[2ull * 64 * 1024 * 64];       // 16.8 MiB

__device__ __forceinline__ unsigned packh2(float x, float y) {
    __half2 h = __float22half2_rn(make_float2(x, y));
    return *reinterpret_cast<unsigned*>(&h);
}

__device__ __forceinline__ void mma_f16(float c[4], const unsigned a[4],
                                        unsigned b0, unsigned b1) {
    asm volatile(
        "mma.sync.aligned.m16n8k16.row.col.f32.f16.f16.f32 "
        "{%0,%1,%2,%3}, {%4,%5,%6,%7}, {%8,%9}, {%0,%1,%2,%3};\n"
        : "+f"(c[0]), "+f"(c[1]), "+f"(c[2]), "+f"(c[3])
        : "r"(a[0]), "r"(a[1]), "r"(a[2]), "r"(a[3]), "r"(b0), "r"(b1));
}

__device__ __forceinline__ void ldsm4(unsigned r[4], unsigned saddr) {
    asm volatile(
        "ldmatrix.sync.aligned.m8n8.x4.shared.b16 {%0,%1,%2,%3}, [%4];\n"
        : "=r"(r[0]), "=r"(r[1]), "=r"(r[2]), "=r"(r[3]) : "r"(saddr));
}

__device__ __forceinline__ void ldsm4t(unsigned r[4], unsigned saddr) {
    asm volatile(
        "ldmatrix.sync.aligned.m8n8.x4.trans.shared.b16 {%0,%1,%2,%3}, [%4];\n"
        : "=r"(r[0]), "=r"(r[1]), "=r"(r[2]), "=r"(r[3]) : "r"(saddr));
}

__device__ __forceinline__ void cpa16(unsigned sdst, const void* gsrc) {
    asm volatile("cp.async.cg.shared.global [%0], [%1], 16;\n"
                 :: "r"(sdst), "l"(gsrc));
}
#define CPA_COMMIT() asm volatile("cp.async.commit_group;\n")
#define CPA_WAIT1()  asm volatile("cp.async.wait_group 1;\n")
#define CPA_WAIT0()  asm volatile("cp.async.wait_group 0;\n")

// ---------------------------------------------------------------------------
// Kernel 0: K/V fp32 -> fp16 (same rounding as before; pure relayout).
// ---------------------------------------------------------------------------
__global__ __launch_bounds__(256) void k_cvt(
    const float* __restrict__ K, const float* __restrict__ V)
{
    unsigned i = blockIdx.x * 256u + threadIdx.x;      // float4 index, 2^21 total
    const float4* src = (i < 1048576u)
        ? reinterpret_cast<const float4*>(K)
        : reinterpret_cast<const float4*>(V) - 1048576;
    float4 v = src[i];
    uint2 st;
    st.x = packh2(v.x, v.y);
    st.y = packh2(v.z, v.w);
    reinterpret_cast<uint2*>(g_kv)[i] = st;
}

// ---------------------------------------------------------------------------
// Kernel 1: bias = sum_c dtw*W + b - 4 (exp offset folded); masked -> -60000.
// Thread covers rows (q, q+8) x 4 keys -> one uint4 scratch store per head.
// ---------------------------------------------------------------------------
__global__ __launch_bounds__(256) void k_bias(
    const float* __restrict__ dtw, const int* __restrict__ mask,
    const float* __restrict__ W, const float* __restrict__ bvec)
{
    __shared__ float Ws[HH * CC];
    __shared__ float bs[HH];
    int t = threadIdx.x;
    if (t < HH * CC) Ws[t] = W[t];
    if (t < HH)      bs[t] = bvec[t] - 4.0f;
    __syncthreads();

    unsigned idx = blockIdx.x * 256u + (unsigned)t;  // [bb:3][qg:6][r:3][k4:8]
    int k4 = idx & 255;
    int r  = (idx >> 8) & 7;
    int qg = (idx >> 11) & 63;
    int bb = idx >> 17;
    int qlo = qg * 16 + r;

    const float4* dp = reinterpret_cast<const float4*>(dtw)
                       + ((size_t)(bb * CC) * SB + qlo) * 256 + k4;
    const int4* mp = reinterpret_cast<const int4*>(mask)
                     + ((size_t)bb * SB + qlo) * 256 + k4;
    int4 mlo = mp[0];
    int4 mhi = mp[8 * 256];

    float4 a[HH];
    uint2  lo[HH];

#pragma unroll
    for (int h = 0; h < HH; h++) a[h] = make_float4(bs[h], bs[h], bs[h], bs[h]);
#pragma unroll
    for (int c = 0; c < CC; c++) {
        float4 d = __ldcs(dp + (size_t)c * (SB * 256));
#pragma unroll
        for (int h = 0; h < HH; h++) {
            float w = Ws[h * CC + c];
            a[h].x += w * d.x; a[h].y += w * d.y;
            a[h].z += w * d.z; a[h].w += w * d.w;
        }
    }
#pragma unroll
    for (int h = 0; h < HH; h++) {
        lo[h].x = packh2(mlo.x ? a[h].x : -60000.f, mlo.y ? a[h].y : -60000.f);
        lo[h].y = packh2(mlo.z ? a[h].z : -60000.f, mlo.w ? a[h].w : -60000.f);
    }

#pragma unroll
    for (int h = 0; h < HH; h++) a[h] = make_float4(bs[h], bs[h], bs[h], bs[h]);
#pragma unroll
    for (int c = 0; c < CC; c++) {
        float4 d = __ldcs(dp + (size_t)c * (SB * 256) + 8 * 256);
#pragma unroll
        for (int h = 0; h < HH; h++) {
            float w = Ws[h * CC + c];
            a[h].x += w * d.x; a[h].y += w * d.y;
            a[h].z += w * d.z; a[h].w += w * d.w;
        }
    }

    size_t base4 = ((size_t)(bb * HH) * 64 + qg) * 2048
                 + (size_t)(k4 >> 1) * 16 + r * 2 + (k4 & 1);
#pragma unroll
    for (int h = 0; h < HH; h++) {
        uint4 v;
        v.x = lo[h].x;
        v.y = packh2(mhi.x ? a[h].x : -60000.f, mhi.y ? a[h].y : -60000.f);
        v.z = lo[h].y;
        v.w = packh2(mhi.z ? a[h].z : -60000.f, mhi.w ? a[h].w : -60000.f);
        g_scr[base4 + (size_t)h * (64 * 2048)] = v;
    }
}

// ---------------------------------------------------------------------------
// Kernel 2: single-QK-pass attention; fp16 K/V via cp.async double buffer;
// scratch fragments register-prefetched; V B-frags via ldmatrix.trans.
// ---------------------------------------------------------------------------
__global__ __launch_bounds__(256, 3) void k_flash(
    const float* __restrict__ Q, float* __restrict__ out)
{
    __shared__ unsigned Bu[2][128 * KPU];

    const int tid  = threadIdx.x;
    const int warp = tid >> 5;
    const int lane = tid & 31;
    const int g    = lane >> 2;
    const int tg   = lane & 3;

    const int bh = blockIdx.x >> 3;
    const int q8 = blockIdx.x & 7;
    const int qg = q8 * 8 + warp;
    const int wb = warp * 16;

    const float*  Qg = Q + ((size_t)bh * SB + q8 * 128 + wb) * DD;
    const __half* Kh = g_kv + (size_t)bh * (SB * DD);
    const __half* Vh = g_kv + (size_t)(64 + bh) * (SB * DD);
    float* attnW = out + OUT_ELEMS + ((size_t)bh * SB + q8 * 128 + wb) * SB;
    float* outW  = out + ((size_t)bh * SB + q8 * 128 + wb) * DD;
    uint2* scrW  = reinterpret_cast<uint2*>(g_scr)
                 + ((size_t)bh * 64 + qg) * 4096 + lane;

    const unsigned sB0 = (unsigned)__cvta_generic_to_shared(&Bu[0][0]);
    const unsigned sB1 = sB0 + 128 * KPU * 4;

    // chunk loader: 128 keys x 64 halves (row 128B + 16B pad), 4 cp.async/thread
    auto load_chunk = [&](unsigned sbuf, const __half* src) {
#pragma unroll
        for (int j = 0; j < 4; j++) {
            int i = tid + j * 256;
            int r = i >> 3, u = i & 7;
            cpa16(sbuf + r * (KPU * 4) + u * 16, src + r * 64 + u * 8);
        }
    };

    // ---- Q fragments (rows wb+g, wb+g+8), 1/8 folded ----
    unsigned aq[4][4];
#pragma unroll
    for (int ks = 0; ks < 4; ks++) {
        float2 v0 = *reinterpret_cast<const float2*>(Qg + g * DD + ks * 16 + tg * 2);
        float2 v1 = *reinterpret_cast<const float2*>(Qg + (g + 8) * DD + ks * 16 + tg * 2);
        float2 v2 = *reinterpret_cast<const float2*>(Qg + g * DD + ks * 16 + 8 + tg * 2);
        float2 v3 = *reinterpret_cast<const float2*>(Qg + (g + 8) * DD + ks * 16 + 8 + tg * 2);
        aq[ks][0] = packh2(v0.x * 0.125f, v0.y * 0.125f);
        aq[ks][1] = packh2(v1.x * 0.125f, v1.y * 0.125f);
        aq[ks][2] = packh2(v2.x * 0.125f, v2.y * 0.125f);
        aq[ks][3] = packh2(v3.x * 0.125f, v3.y * 0.125f);
    }

    // ---- Pass 1: e = exp(QK/8 + bias') -> scratch; l accumulated ----
    const unsigned laneK = (lane & 7) * (KPU * 4) + (lane >> 3) * 16;
    float l0 = 0.f, l1 = 0.f;

    load_chunk(sB0, Kh);
    CPA_COMMIT();

    for (int ch = 0; ch < 8; ++ch) {
        if (ch < 7) {
            load_chunk((ch & 1) ? sB0 : sB1, Kh + (size_t)(ch + 1) * 8192);
            CPA_COMMIT();
            CPA_WAIT1();
        } else {
            CPA_WAIT0();
        }
        __syncthreads();

        const unsigned sb = (ch & 1) ? sB1 : sB0;
        uint2 bf[4];
#pragma unroll
        for (int p = 0; p < 4; p++) bf[p] = scrW[(ch * 16 + p) * 32];

#pragma unroll
        for (int t8 = 0; t8 < 16; t8++) {
            uint2 ef = bf[t8 & 3];
            if (t8 < 12) bf[t8 & 3] = scrW[(ch * 16 + t8 + 4) * 32];

            unsigned qv[4], qw[4];
            ldsm4(qv, sb + t8 * (8 * KPU * 4) + laneK);
            ldsm4(qw, sb + t8 * (8 * KPU * 4) + laneK + 64);
            float c4[4] = {0.f, 0.f, 0.f, 0.f};
            mma_f16(c4, aq[0], qv[0], qv[1]);
            mma_f16(c4, aq[1], qv[2], qv[3]);
            mma_f16(c4, aq[2], qw[0], qw[1]);
            mma_f16(c4, aq[3], qw[2], qw[3]);

            float2 f0 = __half22float2(*reinterpret_cast<__half2*>(&ef.x));
            float2 f1 = __half22float2(*reinterpret_cast<__half2*>(&ef.y));
            float e0 = __expf(c4[0] + f0.x);
            float e1 = __expf(c4[1] + f0.y);
            float e2 = __expf(c4[2] + f1.x);
            float e3 = __expf(c4[3] + f1.y);
            l0 += e0 + e1;
            l1 += e2 + e3;
            uint2 st;
            st.x = packh2(e0, e1);
            st.y = packh2(e2, e3);
            scrW[(ch * 16 + t8) * 32] = st;
        }
        __syncthreads();
    }

    l0 += __shfl_xor_sync(0xffffffffu, l0, 1);
    l0 += __shfl_xor_sync(0xffffffffu, l0, 2);
    l1 += __shfl_xor_sync(0xffffffffu, l1, 1);
    l1 += __shfl_xor_sync(0xffffffffu, l1, 2);
    const float r0 = 1.f / l0, r1 = 1.f / l1;

    // ---- Pass 2: attention = e/l; O = (sum e*V)/l ----
    float oc[8][4];
#pragma unroll
    for (int dt = 0; dt < 8; dt++)
#pragma unroll
        for (int j = 0; j < 4; j++) oc[dt][j] = 0.f;

    const unsigned laneV = ((lane & 7) + 8 * ((lane >> 3) & 1)) * (KPU * 4)
                         + (lane >> 4) * 16;

    load_chunk(sB0, Vh);
    CPA_COMMIT();

    for (int ch = 0; ch < 8; ++ch) {
        if (ch < 7) {
            load_chunk((ch & 1) ? sB0 : sB1, Vh + (size_t)(ch + 1) * 8192);
            CPA_COMMIT();
            CPA_WAIT1();
        } else {
            CPA_WAIT0();
        }
        __syncthreads();

        const unsigned sb = (ch & 1) ? sB1 : sB0;
        uint2 pf[2][2];
#pragma unroll
        for (int p = 0; p < 2; p++) {
            pf[p][0] = scrW[(ch * 16 + 2 * p) * 32];
            pf[p][1] = scrW[(ch * 16 + 2 * p + 1) * 32];
        }

#pragma unroll
        for (int kg = 0; kg < 8; kg++) {
            uint2 ef0 = pf[kg & 1][0];
            uint2 ef1 = pf[kg & 1][1];
            if (kg < 6) {
                pf[kg & 1][0] = scrW[(ch * 16 + 2 * kg + 4) * 32];
                pf[kg & 1][1] = scrW[(ch * 16 + 2 * kg + 5) * 32];
            }
            unsigned ap[4] = {ef0.x, ef0.y, ef1.x, ef1.y};

            {   // attention stores (fp32 = e/l)
                int n0 = ch * 128 + kg * 16;
                float2 f0 = __half22float2(*reinterpret_cast<__half2*>(&ef0.x));
                float2 f1 = __half22float2(*reinterpret_cast<__half2*>(&ef0.y));
                float2 f2 = __half22float2(*reinterpret_cast<__half2*>(&ef1.x));
                float2 f3 = __half22float2(*reinterpret_cast<__half2*>(&ef1.y));
                __stcs(reinterpret_cast<float2*>(attnW + (size_t)g * SB + n0 + tg * 2),
                       make_float2(f0.x * r0, f0.y * r0));
                __stcs(reinterpret_cast<float2*>(attnW + (size_t)(g + 8) * SB + n0 + tg * 2),
                       make_float2(f1.x * r1, f1.y * r1));
                __stcs(reinterpret_cast<float2*>(attnW + (size_t)g * SB + n0 + 8 + tg * 2),
                       make_float2(f2.x * r0, f2.y * r0));
                __stcs(reinterpret_cast<float2*>(attnW + (size_t)(g + 8) * SB + n0 + 8 + tg * 2),
                       make_float2(f3.x * r1, f3.y * r1));
            }

#pragma unroll
            for (int dp2 = 0; dp2 < 4; dp2++) {
                unsigned v[4];
                ldsm4t(v, sb + kg * (16 * KPU * 4) + laneV + dp2 * 32);
                mma_f16(oc[dp2 * 2],     ap, v[0], v[1]);
                mma_f16(oc[dp2 * 2 + 1], ap, v[2], v[3]);
            }
        }
        __syncthreads();
    }

    // ---- write O (scaled by 1/l) ----
#pragma unroll
    for (int dt = 0; dt < 8; dt++) {
        int col = dt * 8 + tg * 2;
        *reinterpret_cast<float2*>(outW + (size_t)g * DD + col) =
            make_float2(oc[dt][0] * r0, oc[dt][1] * r0);
        *reinterpret_cast<float2*>(outW + (size_t)(g + 8) * DD + col) =
            make_float2(oc[dt][2] * r1, oc[dt][3] * r1);
    }
}

// ---------------------------------------------------------------------------
extern "C" void kernel_launch(void* const* d_in, const int* in_sizes, int n_in,
                              void* d_out, int out_size)
{
    const float* Q    = (const float*)d_in[0];
    const float* K    = (const float*)d_in[1];
    const float* V    = (const float*)d_in[2];
    const float* dtw  = (const float*)d_in[3];
    const int*   mask = (const int*)d_in[4];
    const float* W    = (const float*)d_in[5];
    const float* bvec = (const float*)d_in[6];
    float*       out  = (float*)d_out;

    k_cvt<<<8192, 256>>>(K, V);
    k_bias<<<4096, 256>>>(dtw, mask, W, bvec);
    k_flash<<<BB * HH * (SB / 128), 256>>>(Q, out);
}

// round 9
// speedup vs baseline: 1.4859x; 1.0438x over previous
#include <cuda_runtime.h>
#include <cuda_fp16.h>
#include <cstdint>

// Problem constants
#define SB   1024
#define DD   64
#define BB   8
#define HH   8
#define CC   21
#define OUT_ELEMS (BB*HH*SB*DD)
#define KPU  36      // smem chunk pitch in uints (72 halves = 144B) -> LDSM conflict-free

// ---------------------------------------------------------------------------
// Scratch 1: fragment-tiled bias/e, [bh(64)][qg(64)][kgrp(128)][lane(32)] uint2.
// Scratch 2: fp16 K and V, [2][bh(64)][s(1024)][d(64)].
// Scratch 3: per-row softmax reciprocals 1/l, [bh(64)][row(1024)].
// ---------------------------------------------------------------------------
__device__ uint4  g_scr[64ull * 64 * 2048];          // 128 MiB
__device__ __half g_kv[2ull * 64 * 1024 * 64];       // 16.8 MiB
__device__ float  g_linv[64 * 1024];                 // 256 KiB

__device__ __forceinline__ unsigned packh2(float x, float y) {
    __half2 h = __float22half2_rn(make_float2(x, y));
    return *reinterpret_cast<unsigned*>(&h);
}

__device__ __forceinline__ void mma_f16(float c[4], const unsigned a[4],
                                        unsigned b0, unsigned b1) {
    asm volatile(
        "mma.sync.aligned.m16n8k16.row.col.f32.f16.f16.f32 "
        "{%0,%1,%2,%3}, {%4,%5,%6,%7}, {%8,%9}, {%0,%1,%2,%3};\n"
        : "+f"(c[0]), "+f"(c[1]), "+f"(c[2]), "+f"(c[3])
        : "r"(a[0]), "r"(a[1]), "r"(a[2]), "r"(a[3]), "r"(b0), "r"(b1));
}

__device__ __forceinline__ void ldsm4(unsigned r[4], unsigned saddr) {
    asm volatile(
        "ldmatrix.sync.aligned.m8n8.x4.shared.b16 {%0,%1,%2,%3}, [%4];\n"
        : "=r"(r[0]), "=r"(r[1]), "=r"(r[2]), "=r"(r[3]) : "r"(saddr));
}

__device__ __forceinline__ void ldsm4t(unsigned r[4], unsigned saddr) {
    asm volatile(
        "ldmatrix.sync.aligned.m8n8.x4.trans.shared.b16 {%0,%1,%2,%3}, [%4];\n"
        : "=r"(r[0]), "=r"(r[1]), "=r"(r[2]), "=r"(r[3]) : "r"(saddr));
}

__device__ __forceinline__ void cpa16(unsigned sdst, const void* gsrc) {
    asm volatile("cp.async.cg.shared.global [%0], [%1], 16;\n"
                 :: "r"(sdst), "l"(gsrc));
}
#define CPA_COMMIT() asm volatile("cp.async.commit_group;\n")
#define CPA_WAIT1()  asm volatile("cp.async.wait_group 1;\n")
#define CPA_WAIT0()  asm volatile("cp.async.wait_group 0;\n")

// ---------------------------------------------------------------------------
// Kernel 0: K/V fp32 -> fp16 relayout.
// ---------------------------------------------------------------------------
__global__ __launch_bounds__(256) void k_cvt(
    const float* __restrict__ K, const float* __restrict__ V)
{
    unsigned i = blockIdx.x * 256u + threadIdx.x;
    const float4* src = (i < 1048576u)
        ? reinterpret_cast<const float4*>(K)
        : reinterpret_cast<const float4*>(V) - 1048576;
    float4 v = src[i];
    uint2 st;
    st.x = packh2(v.x, v.y);
    st.y = packh2(v.z, v.w);
    reinterpret_cast<uint2*>(g_kv)[i] = st;
}

// ---------------------------------------------------------------------------
// Kernel 1: bias = sum_c dtw*W + b - 4; masked -> -60000. Fragment-tiled out.
// ---------------------------------------------------------------------------
__global__ __launch_bounds__(256) void k_bias(
    const float* __restrict__ dtw, const int* __restrict__ mask,
    const float* __restrict__ W, const float* __restrict__ bvec)
{
    __shared__ float Ws[HH * CC];
    __shared__ float bs[HH];
    int t = threadIdx.x;
    if (t < HH * CC) Ws[t] = W[t];
    if (t < HH)      bs[t] = bvec[t] - 4.0f;
    __syncthreads();

    unsigned idx = blockIdx.x * 256u + (unsigned)t;  // [bb:3][qg:6][r:3][k4:8]
    int k4 = idx & 255;
    int r  = (idx >> 8) & 7;
    int qg = (idx >> 11) & 63;
    int bb = idx >> 17;
    int qlo = qg * 16 + r;

    const float4* dp = reinterpret_cast<const float4*>(dtw)
                       + ((size_t)(bb * CC) * SB + qlo) * 256 + k4;
    const int4* mp = reinterpret_cast<const int4*>(mask)
                     + ((size_t)bb * SB + qlo) * 256 + k4;
    int4 mlo = mp[0];
    int4 mhi = mp[8 * 256];

    float4 a[HH];
    uint2  lo[HH];

#pragma unroll
    for (int h = 0; h < HH; h++) a[h] = make_float4(bs[h], bs[h], bs[h], bs[h]);
#pragma unroll
    for (int c = 0; c < CC; c++) {
        float4 d = __ldcs(dp + (size_t)c * (SB * 256));
#pragma unroll
        for (int h = 0; h < HH; h++) {
            float w = Ws[h * CC + c];
            a[h].x += w * d.x; a[h].y += w * d.y;
            a[h].z += w * d.z; a[h].w += w * d.w;
        }
    }
#pragma unroll
    for (int h = 0; h < HH; h++) {
        lo[h].x = packh2(mlo.x ? a[h].x : -60000.f, mlo.y ? a[h].y : -60000.f);
        lo[h].y = packh2(mlo.z ? a[h].z : -60000.f, mlo.w ? a[h].w : -60000.f);
    }

#pragma unroll
    for (int h = 0; h < HH; h++) a[h] = make_float4(bs[h], bs[h], bs[h], bs[h]);
#pragma unroll
    for (int c = 0; c < CC; c++) {
        float4 d = __ldcs(dp + (size_t)c * (SB * 256) + 8 * 256);
#pragma unroll
        for (int h = 0; h < HH; h++) {
            float w = Ws[h * CC + c];
            a[h].x += w * d.x; a[h].y += w * d.y;
            a[h].z += w * d.z; a[h].w += w * d.w;
        }
    }

    size_t base4 = ((size_t)(bb * HH) * 64 + qg) * 2048
                 + (size_t)(k4 >> 1) * 16 + r * 2 + (k4 & 1);
#pragma unroll
    for (int h = 0; h < HH; h++) {
        uint4 v;
        v.x = lo[h].x;
        v.y = packh2(mhi.x ? a[h].x : -60000.f, mhi.y ? a[h].y : -60000.f);
        v.z = lo[h].y;
        v.w = packh2(mhi.z ? a[h].z : -60000.f, mhi.w ? a[h].w : -60000.f);
        g_scr[base4 + (size_t)h * (64 * 2048)] = v;
    }
}

// ---------------------------------------------------------------------------
// Kernel 2: pass 1 — e = exp(QK/8 + bias') -> scratch (fp16); 1/l -> g_linv.
// 4 CTAs/SM -> grid 512 fits in ONE wave.
// ---------------------------------------------------------------------------
__global__ __launch_bounds__(256, 4) void k_pass1(
    const float* __restrict__ Q)
{
    __shared__ unsigned Bu[2][128 * KPU];

    const int tid  = threadIdx.x;
    const int warp = tid >> 5;
    const int lane = tid & 31;
    const int g    = lane >> 2;
    const int tg   = lane & 3;

    const int bh = blockIdx.x >> 3;
    const int q8 = blockIdx.x & 7;
    const int qg = q8 * 8 + warp;
    const int wb = warp * 16;

    const float*  Qg = Q + ((size_t)bh * SB + q8 * 128 + wb) * DD;
    const __half* Kh = g_kv + (size_t)bh * (SB * DD);
    uint2* scrW  = reinterpret_cast<uint2*>(g_scr)
                 + ((size_t)bh * 64 + qg) * 4096 + lane;

    const unsigned sB0 = (unsigned)__cvta_generic_to_shared(&Bu[0][0]);
    const unsigned sB1 = sB0 + 128 * KPU * 4;

    auto load_chunk = [&](unsigned sbuf, const __half* src) {
#pragma unroll
        for (int j = 0; j < 4; j++) {
            int i = tid + j * 256;
            int r = i >> 3, u = i & 7;
            cpa16(sbuf + r * (KPU * 4) + u * 16, src + r * 64 + u * 8);
        }
    };

    // Q fragments (rows wb+g, wb+g+8), 1/8 folded
    unsigned aq[4][4];
#pragma unroll
    for (int ks = 0; ks < 4; ks++) {
        float2 v0 = *reinterpret_cast<const float2*>(Qg + g * DD + ks * 16 + tg * 2);
        float2 v1 = *reinterpret_cast<const float2*>(Qg + (g + 8) * DD + ks * 16 + tg * 2);
        float2 v2 = *reinterpret_cast<const float2*>(Qg + g * DD + ks * 16 + 8 + tg * 2);
        float2 v3 = *reinterpret_cast<const float2*>(Qg + (g + 8) * DD + ks * 16 + 8 + tg * 2);
        aq[ks][0] = packh2(v0.x * 0.125f, v0.y * 0.125f);
        aq[ks][1] = packh2(v1.x * 0.125f, v1.y * 0.125f);
        aq[ks][2] = packh2(v2.x * 0.125f, v2.y * 0.125f);
        aq[ks][3] = packh2(v3.x * 0.125f, v3.y * 0.125f);
    }

    const unsigned laneK = (lane & 7) * (KPU * 4) + (lane >> 3) * 16;
    float l0 = 0.f, l1 = 0.f;

    load_chunk(sB0, Kh);
    CPA_COMMIT();

    for (int ch = 0; ch < 8; ++ch) {
        if (ch < 7) {
            load_chunk((ch & 1) ? sB0 : sB1, Kh + (size_t)(ch + 1) * 8192);
            CPA_COMMIT();
            CPA_WAIT1();
        } else {
            CPA_WAIT0();
        }
        __syncthreads();

        const unsigned sb = (ch & 1) ? sB1 : sB0;
        uint2 bf[4];
#pragma unroll
        for (int p = 0; p < 4; p++) bf[p] = scrW[(ch * 16 + p) * 32];

#pragma unroll
        for (int t8 = 0; t8 < 16; t8++) {
            uint2 ef = bf[t8 & 3];
            if (t8 < 12) bf[t8 & 3] = scrW[(ch * 16 + t8 + 4) * 32];

            unsigned qv[4], qw[4];
            ldsm4(qv, sb + t8 * (8 * KPU * 4) + laneK);
            ldsm4(qw, sb + t8 * (8 * KPU * 4) + laneK + 64);
            float c4[4] = {0.f, 0.f, 0.f, 0.f};
            mma_f16(c4, aq[0], qv[0], qv[1]);
            mma_f16(c4, aq[1], qv[2], qv[3]);
            mma_f16(c4, aq[2], qw[0], qw[1]);
            mma_f16(c4, aq[3], qw[2], qw[3]);

            float2 f0 = __half22float2(*reinterpret_cast<__half2*>(&ef.x));
            float2 f1 = __half22float2(*reinterpret_cast<__half2*>(&ef.y));
            float e0 = __expf(c4[0] + f0.x);
            float e1 = __expf(c4[1] + f0.y);
            float e2 = __expf(c4[2] + f1.x);
            float e3 = __expf(c4[3] + f1.y);
            l0 += e0 + e1;
            l1 += e2 + e3;
            uint2 st;
            st.x = packh2(e0, e1);
            st.y = packh2(e2, e3);
            scrW[(ch * 16 + t8) * 32] = st;
        }
        __syncthreads();
    }

    l0 += __shfl_xor_sync(0xffffffffu, l0, 1);
    l0 += __shfl_xor_sync(0xffffffffu, l0, 2);
    l1 += __shfl_xor_sync(0xffffffffu, l1, 1);
    l1 += __shfl_xor_sync(0xffffffffu, l1, 2);

    if (tg == 0) {
        g_linv[bh * SB + qg * 16 + g]     = 1.f / l0;
        g_linv[bh * SB + qg * 16 + g + 8] = 1.f / l1;
    }
}

// ---------------------------------------------------------------------------
// Kernel 3: pass 2 — attention = e/l (fp32); O = (sum e*V)/l via mma.
// ---------------------------------------------------------------------------
__global__ __launch_bounds__(256, 4) void k_pass2(
    float* __restrict__ out)
{
    __shared__ unsigned Bu[2][128 * KPU];

    const int tid  = threadIdx.x;
    const int warp = tid >> 5;
    const int lane = tid & 31;
    const int g    = lane >> 2;
    const int tg   = lane & 3;

    const int bh = blockIdx.x >> 3;
    const int q8 = blockIdx.x & 7;
    const int qg = q8 * 8 + warp;
    const int wb = warp * 16;

    const __half* Vh = g_kv + (size_t)(64 + bh) * (SB * DD);
    float* attnW = out + OUT_ELEMS + ((size_t)bh * SB + q8 * 128 + wb) * SB;
    float* outW  = out + ((size_t)bh * SB + q8 * 128 + wb) * DD;
    uint2* scrW  = reinterpret_cast<uint2*>(g_scr)
                 + ((size_t)bh * 64 + qg) * 4096 + lane;

    const float r0 = g_linv[bh * SB + qg * 16 + g];
    const float r1 = g_linv[bh * SB + qg * 16 + g + 8];

    const unsigned sB0 = (unsigned)__cvta_generic_to_shared(&Bu[0][0]);
    const unsigned sB1 = sB0 + 128 * KPU * 4;

    auto load_chunk = [&](unsigned sbuf, const __half* src) {
#pragma unroll
        for (int j = 0; j < 4; j++) {
            int i = tid + j * 256;
            int r = i >> 3, u = i & 7;
            cpa16(sbuf + r * (KPU * 4) + u * 16, src + r * 64 + u * 8);
        }
    };

    float oc[8][4];
#pragma unroll
    for (int dt = 0; dt < 8; dt++)
#pragma unroll
        for (int j = 0; j < 4; j++) oc[dt][j] = 0.f;

    const unsigned laneV = ((lane & 7) + 8 * ((lane >> 3) & 1)) * (KPU * 4)
                         + (lane >> 4) * 16;

    load_chunk(sB0, Vh);
    CPA_COMMIT();

    for (int ch = 0; ch < 8; ++ch) {
        if (ch < 7) {
            load_chunk((ch & 1) ? sB0 : sB1, Vh + (size_t)(ch + 1) * 8192);
            CPA_COMMIT();
            CPA_WAIT1();
        } else {
            CPA_WAIT0();
        }
        __syncthreads();

        const unsigned sb = (ch & 1) ? sB1 : sB0;
        uint2 pf[2][2];
#pragma unroll
        for (int p = 0; p < 2; p++) {
            pf[p][0] = scrW[(ch * 16 + 2 * p) * 32];
            pf[p][1] = scrW[(ch * 16 + 2 * p + 1) * 32];
        }

#pragma unroll
        for (int kg = 0; kg < 8; kg++) {
            uint2 ef0 = pf[kg & 1][0];
            uint2 ef1 = pf[kg & 1][1];
            if (kg < 6) {
                pf[kg & 1][0] = scrW[(ch * 16 + 2 * kg + 4) * 32];
                pf[kg & 1][1] = scrW[(ch * 16 + 2 * kg + 5) * 32];
            }
            unsigned ap[4] = {ef0.x, ef0.y, ef1.x, ef1.y};

            {   // attention stores (fp32 = e/l)
                int n0 = ch * 128 + kg * 16;
                float2 f0 = __half22float2(*reinterpret_cast<__half2*>(&ef0.x));
                float2 f1 = __half22float2(*reinterpret_cast<__half2*>(&ef0.y));
                float2 f2 = __half22float2(*reinterpret_cast<__half2*>(&ef1.x));
                float2 f3 = __half22float2(*reinterpret_cast<__half2*>(&ef1.y));
                __stcs(reinterpret_cast<float2*>(attnW + (size_t)g * SB + n0 + tg * 2),
                       make_float2(f0.x * r0, f0.y * r0));
                __stcs(reinterpret_cast<float2*>(attnW + (size_t)(g + 8) * SB + n0 + tg * 2),
                       make_float2(f1.x * r1, f1.y * r1));
                __stcs(reinterpret_cast<float2*>(attnW + (size_t)g * SB + n0 + 8 + tg * 2),
                       make_float2(f2.x * r0, f2.y * r0));
                __stcs(reinterpret_cast<float2*>(attnW + (size_t)(g + 8) * SB + n0 + 8 + tg * 2),
                       make_float2(f3.x * r1, f3.y * r1));
            }

#pragma unroll
            for (int dp2 = 0; dp2 < 4; dp2++) {
                unsigned v[4];
                ldsm4t(v, sb + kg * (16 * KPU * 4) + laneV + dp2 * 32);
                mma_f16(oc[dp2 * 2],     ap, v[0], v[1]);
                mma_f16(oc[dp2 * 2 + 1], ap, v[2], v[3]);
            }
        }
        __syncthreads();
    }

#pragma unroll
    for (int dt = 0; dt < 8; dt++) {
        int col = dt * 8 + tg * 2;
        *reinterpret_cast<float2*>(outW + (size_t)g * DD + col) =
            make_float2(oc[dt][0] * r0, oc[dt][1] * r0);
        *reinterpret_cast<float2*>(outW + (size_t)(g + 8) * DD + col) =
            make_float2(oc[dt][2] * r1, oc[dt][3] * r1);
    }
}

// ---------------------------------------------------------------------------
extern "C" void kernel_launch(void* const* d_in, const int* in_sizes, int n_in,
                              void* d_out, int out_size)
{
    const float* Q    = (const float*)d_in[0];
    const float* K    = (const float*)d_in[1];
    const float* V    = (const float*)d_in[2];
    const float* dtw  = (const float*)d_in[3];
    const int*   mask = (const int*)d_in[4];
    const float* W    = (const float*)d_in[5];
    const float* bvec = (const float*)d_in[6];
    float*       out  = (float*)d_out;

    k_cvt<<<8192, 256>>>(K, V);
    k_bias<<<4096, 256>>>(dtw, mask, W, bvec);
    k_pass1<<<BB * HH * (SB / 128), 256>>>(Q);
    k_pass2<<<BB * HH * (SB / 128), 256>>>(out);
}

// round 10
// speedup vs baseline: 1.5065x; 1.0139x over previous
#include <cuda_runtime.h>
#include <cuda_fp16.h>
#include <cstdint>

// Problem constants
#define SB   1024
#define DD   64
#define BB   8
#define HH   8
#define CC   21
#define OUT_ELEMS (BB*HH*SB*DD)
#define KPU  36      // smem chunk pitch in uints (72 halves = 144B) -> LDSM conflict-free

// ---------------------------------------------------------------------------
// Scratch 1: fragment-tiled bias/e, [bh(64)][qg(64)][kgrp(128)][lane(32)] uint2.
// Scratch 2: fp16 K and V, [2][bh(64)][s(1024)][d(64)].
// Scratch 3: per-row softmax reciprocals 1/l, [bh(64)][row(1024)].
// ---------------------------------------------------------------------------
__device__ uint4  g_scr[64ull * 64 * 2048];          // 128 MiB
__device__ __half g_kv[2ull * 64 * 1024 * 64];       // 16.8 MiB
__device__ float  g_linv[64 * 1024];                 // 256 KiB

__device__ __forceinline__ unsigned packh2(float x, float y) {
    __half2 h = __float22half2_rn(make_float2(x, y));
    return *reinterpret_cast<unsigned*>(&h);
}

__device__ __forceinline__ void mma_f16(float c[4], const unsigned a[4],
                                        unsigned b0, unsigned b1) {
    asm volatile(
        "mma.sync.aligned.m16n8k16.row.col.f32.f16.f16.f32 "
        "{%0,%1,%2,%3}, {%4,%5,%6,%7}, {%8,%9}, {%0,%1,%2,%3};\n"
        : "+f"(c[0]), "+f"(c[1]), "+f"(c[2]), "+f"(c[3])
        : "r"(a[0]), "r"(a[1]), "r"(a[2]), "r"(a[3]), "r"(b0), "r"(b1));
}

__device__ __forceinline__ void ldsm4(unsigned r[4], unsigned saddr) {
    asm volatile(
        "ldmatrix.sync.aligned.m8n8.x4.shared.b16 {%0,%1,%2,%3}, [%4];\n"
        : "=r"(r[0]), "=r"(r[1]), "=r"(r[2]), "=r"(r[3]) : "r"(saddr));
}

__device__ __forceinline__ void ldsm4t(unsigned r[4], unsigned saddr) {
    asm volatile(
        "ldmatrix.sync.aligned.m8n8.x4.trans.shared.b16 {%0,%1,%2,%3}, [%4];\n"
        : "=r"(r[0]), "=r"(r[1]), "=r"(r[2]), "=r"(r[3]) : "r"(saddr));
}

__device__ __forceinline__ void cpa16(unsigned sdst, const void* gsrc) {
    asm volatile("cp.async.cg.shared.global [%0], [%1], 16;\n"
                 :: "r"(sdst), "l"(gsrc));
}
#define CPA_COMMIT() asm volatile("cp.async.commit_group;\n")
#define CPA_WAIT1()  asm volatile("cp.async.wait_group 1;\n")
#define CPA_WAIT0()  asm volatile("cp.async.wait_group 0;\n")

// ---------------------------------------------------------------------------
// Kernel 1 (fused): blocks [0,2048) convert K/V fp32->fp16; blocks [2048,6144)
// compute bias = sum_c dtw*W + b - 4 (masked -> -60000), fragment-tiled.
// ---------------------------------------------------------------------------
__global__ __launch_bounds__(256) void k_biascvt(
    const float* __restrict__ dtw, const int* __restrict__ mask,
    const float* __restrict__ W, const float* __restrict__ bvec,
    const float* __restrict__ K, const float* __restrict__ V)
{
    if (blockIdx.x < 2048) {
        // ---- K/V conversion: 2048 blocks x 256 thr x 4 float4 = 2M float4 ----
        unsigned i0 = blockIdx.x * 256u + threadIdx.x;
#pragma unroll
        for (int j = 0; j < 4; j++) {
            unsigned i = i0 + j * 524288u;
            const float4* src = (i < 1048576u)
                ? reinterpret_cast<const float4*>(K)
                : reinterpret_cast<const float4*>(V) - 1048576;
            float4 v = src[i];
            uint2 st;
            st.x = packh2(v.x, v.y);
            st.y = packh2(v.z, v.w);
            reinterpret_cast<uint2*>(g_kv)[i] = st;
        }
        return;
    }

    __shared__ float Ws[HH * CC];
    __shared__ float bs[HH];
    int t = threadIdx.x;
    if (t < HH * CC) Ws[t] = W[t];
    if (t < HH)      bs[t] = bvec[t] - 4.0f;
    __syncthreads();

    unsigned idx = (blockIdx.x - 2048) * 256u + (unsigned)t;  // [bb:3][qg:6][r:3][k4:8]
    int k4 = idx & 255;
    int r  = (idx >> 8) & 7;
    int qg = (idx >> 11) & 63;
    int bb = idx >> 17;
    int qlo = qg * 16 + r;

    const float4* dp = reinterpret_cast<const float4*>(dtw)
                       + ((size_t)(bb * CC) * SB + qlo) * 256 + k4;
    const int4* mp = reinterpret_cast<const int4*>(mask)
                     + ((size_t)bb * SB + qlo) * 256 + k4;
    int4 mlo = mp[0];
    int4 mhi = mp[8 * 256];

    float4 a[HH];
    uint2  lo[HH];

#pragma unroll
    for (int h = 0; h < HH; h++) a[h] = make_float4(bs[h], bs[h], bs[h], bs[h]);
#pragma unroll
    for (int c = 0; c < CC; c++) {
        float4 d = __ldcs(dp + (size_t)c * (SB * 256));
#pragma unroll
        for (int h = 0; h < HH; h++) {
            float w = Ws[h * CC + c];
            a[h].x += w * d.x; a[h].y += w * d.y;
            a[h].z += w * d.z; a[h].w += w * d.w;
        }
    }
#pragma unroll
    for (int h = 0; h < HH; h++) {
        lo[h].x = packh2(mlo.x ? a[h].x : -60000.f, mlo.y ? a[h].y : -60000.f);
        lo[h].y = packh2(mlo.z ? a[h].z : -60000.f, mlo.w ? a[h].w : -60000.f);
    }

#pragma unroll
    for (int h = 0; h < HH; h++) a[h] = make_float4(bs[h], bs[h], bs[h], bs[h]);
#pragma unroll
    for (int c = 0; c < CC; c++) {
        float4 d = __ldcs(dp + (size_t)c * (SB * 256) + 8 * 256);
#pragma unroll
        for (int h = 0; h < HH; h++) {
            float w = Ws[h * CC + c];
            a[h].x += w * d.x; a[h].y += w * d.y;
            a[h].z += w * d.z; a[h].w += w * d.w;
        }
    }

    size_t base4 = ((size_t)(bb * HH) * 64 + qg) * 2048
                 + (size_t)(k4 >> 1) * 16 + r * 2 + (k4 & 1);
#pragma unroll
    for (int h = 0; h < HH; h++) {
        uint4 v;
        v.x = lo[h].x;
        v.y = packh2(mhi.x ? a[h].x : -60000.f, mhi.y ? a[h].y : -60000.f);
        v.z = lo[h].y;
        v.w = packh2(mhi.z ? a[h].z : -60000.f, mhi.w ? a[h].w : -60000.f);
        g_scr[base4 + (size_t)h * (64 * 2048)] = v;
    }
}

// ---------------------------------------------------------------------------
// Kernel 2: pass 1 — e = exp(QK/8 + bias') -> scratch (fp16); 1/l -> g_linv.
// ---------------------------------------------------------------------------
__global__ __launch_bounds__(256, 4) void k_pass1(
    const float* __restrict__ Q)
{
    __shared__ unsigned Bu[2][128 * KPU];

    const int tid  = threadIdx.x;
    const int warp = tid >> 5;
    const int lane = tid & 31;
    const int g    = lane >> 2;
    const int tg   = lane & 3;

    const int bh = blockIdx.x >> 3;
    const int q8 = blockIdx.x & 7;
    const int qg = q8 * 8 + warp;
    const int wb = warp * 16;

    const float*  Qg = Q + ((size_t)bh * SB + q8 * 128 + wb) * DD;
    const __half* Kh = g_kv + (size_t)bh * (SB * DD);
    uint2* scrW  = reinterpret_cast<uint2*>(g_scr)
                 + ((size_t)bh * 64 + qg) * 4096 + lane;

    const unsigned sB0 = (unsigned)__cvta_generic_to_shared(&Bu[0][0]);
    const unsigned sB1 = sB0 + 128 * KPU * 4;

    auto load_chunk = [&](unsigned sbuf, const __half* src) {
#pragma unroll
        for (int j = 0; j < 4; j++) {
            int i = tid + j * 256;
            int r = i >> 3, u = i & 7;
            cpa16(sbuf + r * (KPU * 4) + u * 16, src + r * 64 + u * 8);
        }
    };

    unsigned aq[4][4];
#pragma unroll
    for (int ks = 0; ks < 4; ks++) {
        float2 v0 = *reinterpret_cast<const float2*>(Qg + g * DD + ks * 16 + tg * 2);
        float2 v1 = *reinterpret_cast<const float2*>(Qg + (g + 8) * DD + ks * 16 + tg * 2);
        float2 v2 = *reinterpret_cast<const float2*>(Qg + g * DD + ks * 16 + 8 + tg * 2);
        float2 v3 = *reinterpret_cast<const float2*>(Qg + (g + 8) * DD + ks * 16 + 8 + tg * 2);
        aq[ks][0] = packh2(v0.x * 0.125f, v0.y * 0.125f);
        aq[ks][1] = packh2(v1.x * 0.125f, v1.y * 0.125f);
        aq[ks][2] = packh2(v2.x * 0.125f, v2.y * 0.125f);
        aq[ks][3] = packh2(v3.x * 0.125f, v3.y * 0.125f);
    }

    const unsigned laneK = (lane & 7) * (KPU * 4) + (lane >> 3) * 16;
    float l0 = 0.f, l1 = 0.f;

    load_chunk(sB0, Kh);
    CPA_COMMIT();

    for (int ch = 0; ch < 8; ++ch) {
        if (ch < 7) {
            load_chunk((ch & 1) ? sB0 : sB1, Kh + (size_t)(ch + 1) * 8192);
            CPA_COMMIT();
            CPA_WAIT1();
        } else {
            CPA_WAIT0();
        }
        __syncthreads();

        const unsigned sb = (ch & 1) ? sB1 : sB0;
        uint2 bf[4];
#pragma unroll
        for (int p = 0; p < 4; p++) bf[p] = scrW[(ch * 16 + p) * 32];

#pragma unroll
        for (int t8 = 0; t8 < 16; t8++) {
            uint2 ef = bf[t8 & 3];
            if (t8 < 12) bf[t8 & 3] = scrW[(ch * 16 + t8 + 4) * 32];

            unsigned qv[4], qw[4];
            ldsm4(qv, sb + t8 * (8 * KPU * 4) + laneK);
            ldsm4(qw, sb + t8 * (8 * KPU * 4) + laneK + 64);
            float c4[4] = {0.f, 0.f, 0.f, 0.f};
            mma_f16(c4, aq[0], qv[0], qv[1]);
            mma_f16(c4, aq[1], qv[2], qv[3]);
            mma_f16(c4, aq[2], qw[0], qw[1]);
            mma_f16(c4, aq[3], qw[2], qw[3]);

            float2 f0 = __half22float2(*reinterpret_cast<__half2*>(&ef.x));
            float2 f1 = __half22float2(*reinterpret_cast<__half2*>(&ef.y));
            float e0 = __expf(c4[0] + f0.x);
            float e1 = __expf(c4[1] + f0.y);
            float e2 = __expf(c4[2] + f1.x);
            float e3 = __expf(c4[3] + f1.y);
            l0 += e0 + e1;
            l1 += e2 + e3;
            uint2 st;
            st.x = packh2(e0, e1);
            st.y = packh2(e2, e3);
            scrW[(ch * 16 + t8) * 32] = st;
        }
        __syncthreads();
    }

    l0 += __shfl_xor_sync(0xffffffffu, l0, 1);
    l0 += __shfl_xor_sync(0xffffffffu, l0, 2);
    l1 += __shfl_xor_sync(0xffffffffu, l1, 1);
    l1 += __shfl_xor_sync(0xffffffffu, l1, 2);

    if (tg == 0) {
        g_linv[bh * SB + qg * 16 + g]     = 1.f / l0;
        g_linv[bh * SB + qg * 16 + g + 8] = 1.f / l1;
    }
}

// ---------------------------------------------------------------------------
// Kernel 3: pass 2 — attention = e/l (fp32, STG.128 via quad shuffles);
// O = (sum e*V)/l via mma.
// ---------------------------------------------------------------------------
__global__ __launch_bounds__(256, 4) void k_pass2(
    float* __restrict__ out)
{
    __shared__ unsigned Bu[2][128 * KPU];

    const int tid  = threadIdx.x;
    const int warp = tid >> 5;
    const int lane = tid & 31;
    const int g    = lane >> 2;
    const int tg   = lane & 3;

    const int bh = blockIdx.x >> 3;
    const int q8 = blockIdx.x & 7;
    const int qg = q8 * 8 + warp;
    const int wb = warp * 16;

    const __half* Vh = g_kv + (size_t)(64 + bh) * (SB * DD);
    float* attnW = out + OUT_ELEMS + ((size_t)bh * SB + q8 * 128 + wb) * SB;
    float* outW  = out + ((size_t)bh * SB + q8 * 128 + wb) * DD;
    uint2* scrW  = reinterpret_cast<uint2*>(g_scr)
                 + ((size_t)bh * 64 + qg) * 4096 + lane;

    const float r0 = g_linv[bh * SB + qg * 16 + g];
    const float r1 = g_linv[bh * SB + qg * 16 + g + 8];

    const unsigned sB0 = (unsigned)__cvta_generic_to_shared(&Bu[0][0]);
    const unsigned sB1 = sB0 + 128 * KPU * 4;

    auto load_chunk = [&](unsigned sbuf, const __half* src) {
#pragma unroll
        for (int j = 0; j < 4; j++) {
            int i = tid + j * 256;
            int r = i >> 3, u = i & 7;
            cpa16(sbuf + r * (KPU * 4) + u * 16, src + r * 64 + u * 8);
        }
    };

    float oc[8][4];
#pragma unroll
    for (int dt = 0; dt < 8; dt++)
#pragma unroll
        for (int j = 0; j < 4; j++) oc[dt][j] = 0.f;

    const unsigned laneV = ((lane & 7) + 8 * ((lane >> 3) & 1)) * (KPU * 4)
                         + (lane >> 4) * 16;
    const int srcA = (lane & ~3) | ((2 * tg) & 3);
    const int srcB = (lane & ~3) | ((2 * tg + 1) & 3);

    load_chunk(sB0, Vh);
    CPA_COMMIT();

    for (int ch = 0; ch < 8; ++ch) {
        if (ch < 7) {
            load_chunk((ch & 1) ? sB0 : sB1, Vh + (size_t)(ch + 1) * 8192);
            CPA_COMMIT();
            CPA_WAIT1();
        } else {
            CPA_WAIT0();
        }
        __syncthreads();

        const unsigned sb = (ch & 1) ? sB1 : sB0;
        uint2 pf[2][2];
#pragma unroll
        for (int p = 0; p < 2; p++) {
            pf[p][0] = __ldcs(&scrW[(ch * 16 + 2 * p) * 32]);
            pf[p][1] = __ldcs(&scrW[(ch * 16 + 2 * p + 1) * 32]);
        }

#pragma unroll
        for (int kg = 0; kg < 8; kg++) {
            uint2 ef0 = pf[kg & 1][0];
            uint2 ef1 = pf[kg & 1][1];
            if (kg < 6) {
                pf[kg & 1][0] = __ldcs(&scrW[(ch * 16 + 2 * kg + 4) * 32]);
                pf[kg & 1][1] = __ldcs(&scrW[(ch * 16 + 2 * kg + 5) * 32]);
            }
            unsigned ap[4] = {ef0.x, ef0.y, ef1.x, ef1.y};

            {   // attention stores: quad-shuffled into float4 (16 cols/row)
                int n0 = ch * 128 + kg * 16;
                // row g
                unsigned aL = __shfl_sync(0xffffffffu, ef0.x, srcA);
                unsigned bL = __shfl_sync(0xffffffffu, ef0.x, srcB);
                unsigned aH = __shfl_sync(0xffffffffu, ef1.x, srcA);
                unsigned bH = __shfl_sync(0xffffffffu, ef1.x, srcB);
                unsigned pa = (tg < 2) ? aL : aH;
                unsigned pb = (tg < 2) ? bL : bH;
                float2 fa = __half22float2(*reinterpret_cast<__half2*>(&pa));
                float2 fb = __half22float2(*reinterpret_cast<__half2*>(&pb));
                __stcs(reinterpret_cast<float4*>(attnW + (size_t)g * SB + n0 + 4 * tg),
                       make_float4(fa.x * r0, fa.y * r0, fb.x * r0, fb.y * r0));
                // row g+8
                aL = __shfl_sync(0xffffffffu, ef0.y, srcA);
                bL = __shfl_sync(0xffffffffu, ef0.y, srcB);
                aH = __shfl_sync(0xffffffffu, ef1.y, srcA);
                bH = __shfl_sync(0xffffffffu, ef1.y, srcB);
                pa = (tg < 2) ? aL : aH;
                pb = (tg < 2) ? bL : bH;
                fa = __half22float2(*reinterpret_cast<__half2*>(&pa));
                fb = __half22float2(*reinterpret_cast<__half2*>(&pb));
                __stcs(reinterpret_cast<float4*>(attnW + (size_t)(g + 8) * SB + n0 + 4 * tg),
                       make_float4(fa.x * r1, fa.y * r1, fb.x * r1, fb.y * r1));
            }

#pragma unroll
            for (int dp2 = 0; dp2 < 4; dp2++) {
                unsigned v[4];
                ldsm4t(v, sb + kg * (16 * KPU * 4) + laneV + dp2 * 32);
                mma_f16(oc[dp2 * 2],     ap, v[0], v[1]);
                mma_f16(oc[dp2 * 2 + 1], ap, v[2], v[3]);
            }
        }
        __syncthreads();
    }

#pragma unroll
    for (int dt = 0; dt < 8; dt++) {
        int col = dt * 8 + tg * 2;
        *reinterpret_cast<float2*>(outW + (size_t)g * DD + col) =
            make_float2(oc[dt][0] * r0, oc[dt][1] * r0);
        *reinterpret_cast<float2*>(outW + (size_t)(g + 8) * DD + col) =
            make_float2(oc[dt][2] * r1, oc[dt][3] * r1);
    }
}

// ---------------------------------------------------------------------------
extern "C" void kernel_launch(void* const* d_in, const int* in_sizes, int n_in,
                              void* d_out, int out_size)
{
    const float* Q    = (const float*)d_in[0];
    const float* K    = (const float*)d_in[1];
    const float* V    = (const float*)d_in[2];
    const float* dtw  = (const float*)d_in[3];
    const int*   mask = (const int*)d_in[4];
    const float* W    = (const float*)d_in[5];
    const float* bvec = (const float*)d_in[6];
    float*       out  = (float*)d_out;

    k_biascvt<<<6144, 256>>>(dtw, mask, W, bvec, K, V);
    k_pass1<<<BB * HH * (SB / 128), 256>>>(Q);
    k_pass2<<<BB * HH * (SB / 128), 256>>>(out);
}

// round 11
// speedup vs baseline: 1.5298x; 1.0155x over previous
#include <cuda_runtime.h>
#include <cuda_fp16.h>
#include <cstdint>

// Problem constants
#define SB   1024
#define DD   64
#define BB   8
#define HH   8
#define CC   21
#define OUT_ELEMS (BB*HH*SB*DD)
#define KPU  36      // smem chunk pitch in uints (72 halves = 144B) -> LDSM conflict-free

// ---------------------------------------------------------------------------
// Scratch 1: fragment-tiled bias/e, [bh(64)][qg(64)][kgrp(128)][lane(32)] uint2.
// Scratch 2: fp16 K and V, [2][bh(64)][s(1024)][d(64)].
// Scratch 3: per-row softmax reciprocals 1/l, [bh(64)][row(1024)].
// ---------------------------------------------------------------------------
__device__ uint4  g_scr[64ull * 64 * 2048];          // 128 MiB
__device__ __half g_kv[2ull * 64 * 1024 * 64];       // 16.8 MiB
__device__ float  g_linv[64 * 1024];                 // 256 KiB

__device__ __forceinline__ unsigned packh2(float x, float y) {
    __half2 h = __float22half2_rn(make_float2(x, y));
    return *reinterpret_cast<unsigned*>(&h);
}

__device__ __forceinline__ void mma_f16(float c[4], const unsigned a[4],
                                        unsigned b0, unsigned b1) {
    asm volatile(
        "mma.sync.aligned.m16n8k16.row.col.f32.f16.f16.f32 "
        "{%0,%1,%2,%3}, {%4,%5,%6,%7}, {%8,%9}, {%0,%1,%2,%3};\n"
        : "+f"(c[0]), "+f"(c[1]), "+f"(c[2]), "+f"(c[3])
        : "r"(a[0]), "r"(a[1]), "r"(a[2]), "r"(a[3]), "r"(b0), "r"(b1));
}

__device__ __forceinline__ void ldsm4(unsigned r[4], unsigned saddr) {
    asm volatile(
        "ldmatrix.sync.aligned.m8n8.x4.shared.b16 {%0,%1,%2,%3}, [%4];\n"
        : "=r"(r[0]), "=r"(r[1]), "=r"(r[2]), "=r"(r[3]) : "r"(saddr));
}

__device__ __forceinline__ void ldsm4t(unsigned r[4], unsigned saddr) {
    asm volatile(
        "ldmatrix.sync.aligned.m8n8.x4.trans.shared.b16 {%0,%1,%2,%3}, [%4];\n"
        : "=r"(r[0]), "=r"(r[1]), "=r"(r[2]), "=r"(r[3]) : "r"(saddr));
}

__device__ __forceinline__ void cpa16(unsigned sdst, const void* gsrc) {
    asm volatile("cp.async.cg.shared.global [%0], [%1], 16;\n"
                 :: "r"(sdst), "l"(gsrc));
}
#define CPA_COMMIT() asm volatile("cp.async.commit_group;\n")
#define CPA_WAIT1()  asm volatile("cp.async.wait_group 1;\n")
#define CPA_WAIT0()  asm volatile("cp.async.wait_group 0;\n")

// ---------------------------------------------------------------------------
// Kernel 0: K/V fp32 -> fp16 relayout (streaming loads, high occupancy).
// ---------------------------------------------------------------------------
__global__ __launch_bounds__(256) void k_cvt(
    const float* __restrict__ K, const float* __restrict__ V)
{
    unsigned i = blockIdx.x * 256u + threadIdx.x;
    const float4* src = (i < 1048576u)
        ? reinterpret_cast<const float4*>(K)
        : reinterpret_cast<const float4*>(V) - 1048576;
    float4 v = __ldcs(&src[i]);
    uint2 st;
    st.x = packh2(v.x, v.y);
    st.y = packh2(v.z, v.w);
    reinterpret_cast<uint2*>(g_kv)[i] = st;
}

// ---------------------------------------------------------------------------
// Kernel 1: bias = sum_c dtw*W + b - 4; masked -> -60000. Fragment-tiled out.
// ---------------------------------------------------------------------------
__global__ __launch_bounds__(256) void k_bias(
    const float* __restrict__ dtw, const int* __restrict__ mask,
    const float* __restrict__ W, const float* __restrict__ bvec)
{
    __shared__ float Ws[HH * CC];
    __shared__ float bs[HH];
    int t = threadIdx.x;
    if (t < HH * CC) Ws[t] = W[t];
    if (t < HH)      bs[t] = bvec[t] - 4.0f;
    __syncthreads();

    unsigned idx = blockIdx.x * 256u + (unsigned)t;  // [bb:3][qg:6][r:3][k4:8]
    int k4 = idx & 255;
    int r  = (idx >> 8) & 7;
    int qg = (idx >> 11) & 63;
    int bb = idx >> 17;
    int qlo = qg * 16 + r;

    const float4* dp = reinterpret_cast<const float4*>(dtw)
                       + ((size_t)(bb * CC) * SB + qlo) * 256 + k4;
    const int4* mp = reinterpret_cast<const int4*>(mask)
                     + ((size_t)bb * SB + qlo) * 256 + k4;
    int4 mlo = mp[0];
    int4 mhi = mp[8 * 256];

    float4 a[HH];
    uint2  lo[HH];

#pragma unroll
    for (int h = 0; h < HH; h++) a[h] = make_float4(bs[h], bs[h], bs[h], bs[h]);
#pragma unroll
    for (int c = 0; c < CC; c++) {
        float4 d = __ldcs(dp + (size_t)c * (SB * 256));
#pragma unroll
        for (int h = 0; h < HH; h++) {
            float w = Ws[h * CC + c];
            a[h].x += w * d.x; a[h].y += w * d.y;
            a[h].z += w * d.z; a[h].w += w * d.w;
        }
    }
#pragma unroll
    for (int h = 0; h < HH; h++) {
        lo[h].x = packh2(mlo.x ? a[h].x : -60000.f, mlo.y ? a[h].y : -60000.f);
        lo[h].y = packh2(mlo.z ? a[h].z : -60000.f, mlo.w ? a[h].w : -60000.f);
    }

#pragma unroll
    for (int h = 0; h < HH; h++) a[h] = make_float4(bs[h], bs[h], bs[h], bs[h]);
#pragma unroll
    for (int c = 0; c < CC; c++) {
        float4 d = __ldcs(dp + (size_t)c * (SB * 256) + 8 * 256);
#pragma unroll
        for (int h = 0; h < HH; h++) {
            float w = Ws[h * CC + c];
            a[h].x += w * d.x; a[h].y += w * d.y;
            a[h].z += w * d.z; a[h].w += w * d.w;
        }
    }

    size_t base4 = ((size_t)(bb * HH) * 64 + qg) * 2048
                 + (size_t)(k4 >> 1) * 16 + r * 2 + (k4 & 1);
#pragma unroll
    for (int h = 0; h < HH; h++) {
        uint4 v;
        v.x = lo[h].x;
        v.y = packh2(mhi.x ? a[h].x : -60000.f, mhi.y ? a[h].y : -60000.f);
        v.z = lo[h].y;
        v.w = packh2(mhi.z ? a[h].z : -60000.f, mhi.w ? a[h].w : -60000.f);
        g_scr[base4 + (size_t)h * (64 * 2048)] = v;
    }
}

// ---------------------------------------------------------------------------
// Kernel 2: pass 1 — e = exp(QK/8 + bias') -> scratch (fp16); 1/l -> g_linv.
// 4 CTAs/SM -> grid 512 fits in ONE wave.
// ---------------------------------------------------------------------------
__global__ __launch_bounds__(256, 4) void k_pass1(
    const float* __restrict__ Q)
{
    __shared__ unsigned Bu[2][128 * KPU];

    const int tid  = threadIdx.x;
    const int warp = tid >> 5;
    const int lane = tid & 31;
    const int g    = lane >> 2;
    const int tg   = lane & 3;

    const int bh = blockIdx.x >> 3;
    const int q8 = blockIdx.x & 7;
    const int qg = q8 * 8 + warp;
    const int wb = warp * 16;

    const float*  Qg = Q + ((size_t)bh * SB + q8 * 128 + wb) * DD;
    const __half* Kh = g_kv + (size_t)bh * (SB * DD);
    uint2* scrW  = reinterpret_cast<uint2*>(g_scr)
                 + ((size_t)bh * 64 + qg) * 4096 + lane;

    const unsigned sB0 = (unsigned)__cvta_generic_to_shared(&Bu[0][0]);
    const unsigned sB1 = sB0 + 128 * KPU * 4;

    auto load_chunk = [&](unsigned sbuf, const __half* src) {
#pragma unroll
        for (int j = 0; j < 4; j++) {
            int i = tid + j * 256;
            int r = i >> 3, u = i & 7;
            cpa16(sbuf + r * (KPU * 4) + u * 16, src + r * 64 + u * 8);
        }
    };

    unsigned aq[4][4];
#pragma unroll
    for (int ks = 0; ks < 4; ks++) {
        float2 v0 = *reinterpret_cast<const float2*>(Qg + g * DD + ks * 16 + tg * 2);
        float2 v1 = *reinterpret_cast<const float2*>(Qg + (g + 8) * DD + ks * 16 + tg * 2);
        float2 v2 = *reinterpret_cast<const float2*>(Qg + g * DD + ks * 16 + 8 + tg * 2);
        float2 v3 = *reinterpret_cast<const float2*>(Qg + (g + 8) * DD + ks * 16 + 8 + tg * 2);
        aq[ks][0] = packh2(v0.x * 0.125f, v0.y * 0.125f);
        aq[ks][1] = packh2(v1.x * 0.125f, v1.y * 0.125f);
        aq[ks][2] = packh2(v2.x * 0.125f, v2.y * 0.125f);
        aq[ks][3] = packh2(v3.x * 0.125f, v3.y * 0.125f);
    }

    const unsigned laneK = (lane & 7) * (KPU * 4) + (lane >> 3) * 16;
    float l0 = 0.f, l1 = 0.f;

    load_chunk(sB0, Kh);
    CPA_COMMIT();

    for (int ch = 0; ch < 8; ++ch) {
        if (ch < 7) {
            load_chunk((ch & 1) ? sB0 : sB1, Kh + (size_t)(ch + 1) * 8192);
            CPA_COMMIT();
            CPA_WAIT1();
        } else {
            CPA_WAIT0();
        }
        __syncthreads();

        const unsigned sb = (ch & 1) ? sB1 : sB0;
        uint2 bf[4];
#pragma unroll
        for (int p = 0; p < 4; p++) bf[p] = scrW[(ch * 16 + p) * 32];

#pragma unroll
        for (int t8 = 0; t8 < 16; t8++) {
            uint2 ef = bf[t8 & 3];
            if (t8 < 12) bf[t8 & 3] = scrW[(ch * 16 + t8 + 4) * 32];

            unsigned qv[4], qw[4];
            ldsm4(qv, sb + t8 * (8 * KPU * 4) + laneK);
            ldsm4(qw, sb + t8 * (8 * KPU * 4) + laneK + 64);
            float c4[4] = {0.f, 0.f, 0.f, 0.f};
            mma_f16(c4, aq[0], qv[0], qv[1]);
            mma_f16(c4, aq[1], qv[2], qv[3]);
            mma_f16(c4, aq[2], qw[0], qw[1]);
            mma_f16(c4, aq[3], qw[2], qw[3]);

            float2 f0 = __half22float2(*reinterpret_cast<__half2*>(&ef.x));
            float2 f1 = __half22float2(*reinterpret_cast<__half2*>(&ef.y));
            float e0 = __expf(c4[0] + f0.x);
            float e1 = __expf(c4[1] + f0.y);
            float e2 = __expf(c4[2] + f1.x);
            float e3 = __expf(c4[3] + f1.y);
            l0 += e0 + e1;
            l1 += e2 + e3;
            uint2 st;
            st.x = packh2(e0, e1);
            st.y = packh2(e2, e3);
            scrW[(ch * 16 + t8) * 32] = st;
        }
        __syncthreads();
    }

    l0 += __shfl_xor_sync(0xffffffffu, l0, 1);
    l0 += __shfl_xor_sync(0xffffffffu, l0, 2);
    l1 += __shfl_xor_sync(0xffffffffu, l1, 1);
    l1 += __shfl_xor_sync(0xffffffffu, l1, 2);

    if (tg == 0) {
        g_linv[bh * SB + qg * 16 + g]     = 1.f / l0;
        g_linv[bh * SB + qg * 16 + g + 8] = 1.f / l1;
    }
}

// ---------------------------------------------------------------------------
// Kernel 3: pass 2 — attention = e/l (fp32, STG.128 via quad shuffles);
// O = (sum e*V)/l via mma.
// ---------------------------------------------------------------------------
__global__ __launch_bounds__(256, 4) void k_pass2(
    float* __restrict__ out)
{
    __shared__ unsigned Bu[2][128 * KPU];

    const int tid  = threadIdx.x;
    const int warp = tid >> 5;
    const int lane = tid & 31;
    const int g    = lane >> 2;
    const int tg   = lane & 3;

    const int bh = blockIdx.x >> 3;
    const int q8 = blockIdx.x & 7;
    const int qg = q8 * 8 + warp;
    const int wb = warp * 16;

    const __half* Vh = g_kv + (size_t)(64 + bh) * (SB * DD);
    float* attnW = out + OUT_ELEMS + ((size_t)bh * SB + q8 * 128 + wb) * SB;
    float* outW  = out + ((size_t)bh * SB + q8 * 128 + wb) * DD;
    uint2* scrW  = reinterpret_cast<uint2*>(g_scr)
                 + ((size_t)bh * 64 + qg) * 4096 + lane;

    const float r0 = g_linv[bh * SB + qg * 16 + g];
    const float r1 = g_linv[bh * SB + qg * 16 + g + 8];

    const unsigned sB0 = (unsigned)__cvta_generic_to_shared(&Bu[0][0]);
    const unsigned sB1 = sB0 + 128 * KPU * 4;

    auto load_chunk = [&](unsigned sbuf, const __half* src) {
#pragma unroll
        for (int j = 0; j < 4; j++) {
            int i = tid + j * 256;
            int r = i >> 3, u = i & 7;
            cpa16(sbuf + r * (KPU * 4) + u * 16, src + r * 64 + u * 8);
        }
    };

    float oc[8][4];
#pragma unroll
    for (int dt = 0; dt < 8; dt++)
#pragma unroll
        for (int j = 0; j < 4; j++) oc[dt][j] = 0.f;

    const unsigned laneV = ((lane & 7) + 8 * ((lane >> 3) & 1)) * (KPU * 4)
                         + (lane >> 4) * 16;
    const int srcA = (lane & ~3) | ((2 * tg) & 3);
    const int srcB = (lane & ~3) | ((2 * tg + 1) & 3);

    load_chunk(sB0, Vh);
    CPA_COMMIT();

    for (int ch = 0; ch < 8; ++ch) {
        if (ch < 7) {
            load_chunk((ch & 1) ? sB0 : sB1, Vh + (size_t)(ch + 1) * 8192);
            CPA_COMMIT();
            CPA_WAIT1();
        } else {
            CPA_WAIT0();
        }
        __syncthreads();

        const unsigned sb = (ch & 1) ? sB1 : sB0;
        uint2 pf[2][2];
#pragma unroll
        for (int p = 0; p < 2; p++) {
            pf[p][0] = __ldcs(&scrW[(ch * 16 + 2 * p) * 32]);
            pf[p][1] = __ldcs(&scrW[(ch * 16 + 2 * p + 1) * 32]);
        }

#pragma unroll
        for (int kg = 0; kg < 8; kg++) {
            uint2 ef0 = pf[kg & 1][0];
            uint2 ef1 = pf[kg & 1][1];
            if (kg < 6) {
                pf[kg & 1][0] = __ldcs(&scrW[(ch * 16 + 2 * kg + 4) * 32]);
                pf[kg & 1][1] = __ldcs(&scrW[(ch * 16 + 2 * kg + 5) * 32]);
            }
            unsigned ap[4] = {ef0.x, ef0.y, ef1.x, ef1.y};

            {   // attention stores: quad-shuffled into float4 (16 cols/row)
                int n0 = ch * 128 + kg * 16;
                // row g
                unsigned aL = __shfl_sync(0xffffffffu, ef0.x, srcA);
                unsigned bL = __shfl_sync(0xffffffffu, ef0.x, srcB);
                unsigned aH = __shfl_sync(0xffffffffu, ef1.x, srcA);
                unsigned bH = __shfl_sync(0xffffffffu, ef1.x, srcB);
                unsigned pa = (tg < 2) ? aL : aH;
                unsigned pb = (tg < 2) ? bL : bH;
                float2 fa = __half22float2(*reinterpret_cast<__half2*>(&pa));
                float2 fb = __half22float2(*reinterpret_cast<__half2*>(&pb));
                __stcs(reinterpret_cast<float4*>(attnW + (size_t)g * SB + n0 + 4 * tg),
                       make_float4(fa.x * r0, fa.y * r0, fb.x * r0, fb.y * r0));
                // row g+8
                aL = __shfl_sync(0xffffffffu, ef0.y, srcA);
                bL = __shfl_sync(0xffffffffu, ef0.y, srcB);
                aH = __shfl_sync(0xffffffffu, ef1.y, srcA);
                bH = __shfl_sync(0xffffffffu, ef1.y, srcB);
                pa = (tg < 2) ? aL : aH;
                pb = (tg < 2) ? bL : bH;
                fa = __half22float2(*reinterpret_cast<__half2*>(&pa));
                fb = __half22float2(*reinterpret_cast<__half2*>(&pb));
                __stcs(reinterpret_cast<float4*>(attnW + (size_t)(g + 8) * SB + n0 + 4 * tg),
                       make_float4(fa.x * r1, fa.y * r1, fb.x * r1, fb.y * r1));
            }

#pragma unroll
            for (int dp2 = 0; dp2 < 4; dp2++) {
                unsigned v[4];
                ldsm4t(v, sb + kg * (16 * KPU * 4) + laneV + dp2 * 32);
                mma_f16(oc[dp2 * 2],     ap, v[0], v[1]);
                mma_f16(oc[dp2 * 2 + 1], ap, v[2], v[3]);
            }
        }
        __syncthreads();
    }

#pragma unroll
    for (int dt = 0; dt < 8; dt++) {
        int col = dt * 8 + tg * 2;
        *reinterpret_cast<float2*>(outW + (size_t)g * DD + col) =
            make_float2(oc[dt][0] * r0, oc[dt][1] * r0);
        *reinterpret_cast<float2*>(outW + (size_t)(g + 8) * DD + col) =
            make_float2(oc[dt][2] * r1, oc[dt][3] * r1);
    }
}

// ---------------------------------------------------------------------------
extern "C" void kernel_launch(void* const* d_in, const int* in_sizes, int n_in,
                              void* d_out, int out_size)
{
    const float* Q    = (const float*)d_in[0];
    const float* K    = (const float*)d_in[1];
    const float* V    = (const float*)d_in[2];
    const float* dtw  = (const float*)d_in[3];
    const int*   mask = (const int*)d_in[4];
    const float* W    = (const float*)d_in[5];
    const float* bvec = (const float*)d_in[6];
    float*       out  = (float*)d_out;

    k_cvt<<<8192, 256>>>(K, V);
    k_bias<<<4096, 256>>>(dtw, mask, W, bvec);
    k_pass1<<<BB * HH * (SB / 128), 256>>>(Q);
    k_pass2<<<BB * HH * (SB / 128), 256>>>(out);
}